// round 1
// baseline (speedup 1.0000x reference)
#include <cuda_runtime.h>
#include <cuda_bf16.h>
#include <cstdint>

// Problem constants (fixed by setup_inputs)
#define BWIN   4096          // number of windows
#define NTOK   49            // tokens per window (7x7)
#define CDIM   256           // channels
#define NHEAD  8
#define DHEAD  32
#define MROWS  (BWIN * NTOK) // 200704

// ---------------------------------------------------------------------------
// Scratch (device globals; no runtime allocation allowed)
// ---------------------------------------------------------------------------
__device__ float g_qkv[(size_t)MROWS * 768];   // [B*N, 3C] = 616 MB
__device__ float g_att[(size_t)MROWS * CDIM];  // [B*N, C]  = 205 MB

// ---------------------------------------------------------------------------
// SGEMM with bias: C[M,N] = A[M,K] @ B[K,N] + bias[N]
// BM=128, BN=128, BK=16, 256 threads, 8x8 per-thread tile, double-buffered.
// Requires M%128==0, N%128==0, K%16==0 (true for all launches here).
// ---------------------------------------------------------------------------
__global__ __launch_bounds__(256, 2)
void sgemm_bias_kernel(const float* __restrict__ A,
                       const float* __restrict__ B,
                       const float* __restrict__ bias,
                       float* __restrict__ C,
                       int M, int N, int K)
{
    constexpr int BM = 128, BN = 128, BK = 16;
    __shared__ float As[2][BK][BM];   // A stored transposed: As[k][m]
    __shared__ float Bs[2][BK][BN];

    const int tid = threadIdx.x;
    const int bm  = blockIdx.y * BM;
    const int bn  = blockIdx.x * BN;

    const int tx = tid & 15;   // 0..15  (column group)
    const int ty = tid >> 4;   // 0..15  (row group)

    // Global-load mapping
    const int a_row = tid >> 2;         // 0..63  (+64 for second half)
    const int a_k   = (tid & 3) * 4;    // 0,4,8,12
    const int b_k   = tid >> 5;         // 0..7   (+8 for second half)
    const int b_n   = (tid & 31) * 4;   // 0..124

    const float* Ag = A + (size_t)bm * K;
    const float* Bg = B + bn;

    float acc[8][8];
#pragma unroll
    for (int i = 0; i < 8; i++)
#pragma unroll
        for (int j = 0; j < 8; j++) acc[i][j] = 0.f;

    // Prologue: load tile 0
    {
        float4 a0 = *(const float4*)(Ag + (size_t)a_row * K + a_k);
        float4 a1 = *(const float4*)(Ag + (size_t)(a_row + 64) * K + a_k);
        float4 c0 = *(const float4*)(Bg + (size_t)b_k * N + b_n);
        float4 c1 = *(const float4*)(Bg + (size_t)(b_k + 8) * N + b_n);
        As[0][a_k + 0][a_row] = a0.x;  As[0][a_k + 1][a_row] = a0.y;
        As[0][a_k + 2][a_row] = a0.z;  As[0][a_k + 3][a_row] = a0.w;
        As[0][a_k + 0][a_row + 64] = a1.x;  As[0][a_k + 1][a_row + 64] = a1.y;
        As[0][a_k + 2][a_row + 64] = a1.z;  As[0][a_k + 3][a_row + 64] = a1.w;
        *(float4*)&Bs[0][b_k][b_n]     = c0;
        *(float4*)&Bs[0][b_k + 8][b_n] = c1;
    }
    __syncthreads();

    int buf = 0;
    for (int k0 = 0; k0 < K; k0 += BK) {
        const bool more = (k0 + BK) < K;
        float4 na0, na1, nc0, nc1;
        if (more) {
            const float* Ag2 = Ag + (k0 + BK);
            const float* Bg2 = Bg + (size_t)(k0 + BK) * N;
            na0 = *(const float4*)(Ag2 + (size_t)a_row * K + a_k);
            na1 = *(const float4*)(Ag2 + (size_t)(a_row + 64) * K + a_k);
            nc0 = *(const float4*)(Bg2 + (size_t)b_k * N + b_n);
            nc1 = *(const float4*)(Bg2 + (size_t)(b_k + 8) * N + b_n);
        }

#pragma unroll
        for (int kk = 0; kk < BK; kk++) {
            float ar[8], br[8];
            *(float4*)&ar[0] = *(const float4*)&As[buf][kk][ty * 4];
            *(float4*)&ar[4] = *(const float4*)&As[buf][kk][64 + ty * 4];
            *(float4*)&br[0] = *(const float4*)&Bs[buf][kk][tx * 4];
            *(float4*)&br[4] = *(const float4*)&Bs[buf][kk][64 + tx * 4];
#pragma unroll
            for (int i = 0; i < 8; i++)
#pragma unroll
                for (int j = 0; j < 8; j++)
                    acc[i][j] += ar[i] * br[j];
        }

        if (more) {
            const int nb = buf ^ 1;
            As[nb][a_k + 0][a_row] = na0.x;  As[nb][a_k + 1][a_row] = na0.y;
            As[nb][a_k + 2][a_row] = na0.z;  As[nb][a_k + 3][a_row] = na0.w;
            As[nb][a_k + 0][a_row + 64] = na1.x;  As[nb][a_k + 1][a_row + 64] = na1.y;
            As[nb][a_k + 2][a_row + 64] = na1.z;  As[nb][a_k + 3][a_row + 64] = na1.w;
            *(float4*)&Bs[nb][b_k][b_n]     = nc0;
            *(float4*)&Bs[nb][b_k + 8][b_n] = nc1;
        }
        __syncthreads();
        buf ^= 1;
    }

    // Epilogue: bias + store (float4)
#pragma unroll
    for (int ih = 0; ih < 2; ih++) {
#pragma unroll
        for (int i = 0; i < 4; i++) {
            const int row = bm + ih * 64 + ty * 4 + i;
            float* Crow = C + (size_t)row * N;
#pragma unroll
            for (int jh = 0; jh < 2; jh++) {
                const int col = bn + jh * 64 + tx * 4;
                float4 v;
                v.x = acc[ih * 4 + i][jh * 4 + 0] + bias[col + 0];
                v.y = acc[ih * 4 + i][jh * 4 + 1] + bias[col + 1];
                v.z = acc[ih * 4 + i][jh * 4 + 2] + bias[col + 2];
                v.w = acc[ih * 4 + i][jh * 4 + 3] + bias[col + 3];
                *(float4*)(Crow + col) = v;
            }
        }
    }
}

// ---------------------------------------------------------------------------
// Fused windowed attention: one block per (window, head).
// qkv layout per row (768): [q(8 heads x 32) | k(...) | v(...)]
// Computes softmax(q k^T * scale + rel_pos_bias) v and writes [B*N, C] with
// head-interleaved channel layout (matches transpose(0,2,1,3).reshape).
// ---------------------------------------------------------------------------
__global__ __launch_bounds__(256)
void window_attn_kernel(const float* __restrict__ qkv,
                        const float* __restrict__ rpb,   // [169, 8]
                        float* __restrict__ out)
{
    const int b = blockIdx.x;
    const int h = blockIdx.y;

    __shared__ float sq[NTOK * 33];
    __shared__ float sk[NTOK * 33];
    __shared__ float sv[NTOK * 33];
    __shared__ float sp[NTOK * 50];
    __shared__ float srpb[169];

    const int tid = threadIdx.x;
    const float* base = qkv + (size_t)b * NTOK * 768;

    for (int e = tid; e < NTOK * 32; e += 256) {
        const int n = e >> 5, d = e & 31;
        const float* r = base + (size_t)n * 768 + h * 32 + d;
        sq[n * 33 + d] = r[0];
        sk[n * 33 + d] = r[256];
        sv[n * 33 + d] = r[512];
    }
    for (int e = tid; e < 169; e += 256) srpb[e] = rpb[e * 8 + h];
    __syncthreads();

    const float scale = 0.17677669529663687f;  // 32^-0.5
    for (int e = tid; e < NTOK * NTOK; e += 256) {
        const int i = e / NTOK, j = e - i * NTOK;
        float s = 0.f;
#pragma unroll
        for (int d = 0; d < 32; d++) s += sq[i * 33 + d] * sk[j * 33 + d];
        const int xi = i / 7, yi = i - xi * 7;
        const int xj = j / 7, yj = j - xj * 7;
        const int idx = (xi - xj + 6) * 13 + (yi - yj + 6);
        sp[i * 50 + j] = s * scale + srpb[idx];
    }
    __syncthreads();

    // Row softmax: one warp per row (rows strided by 8 warps)
    const int warp = tid >> 5, lane = tid & 31;
    for (int i = warp; i < NTOK; i += 8) {
        float v0 = sp[i * 50 + lane];
        float v1 = (lane + 32 < NTOK) ? sp[i * 50 + lane + 32] : -1e30f;
        float m = fmaxf(v0, v1);
#pragma unroll
        for (int o = 16; o > 0; o >>= 1) m = fmaxf(m, __shfl_xor_sync(0xffffffffu, m, o));
        const float e0 = __expf(v0 - m);
        const float e1 = (lane + 32 < NTOK) ? __expf(v1 - m) : 0.f;
        float s = e0 + e1;
#pragma unroll
        for (int o = 16; o > 0; o >>= 1) s += __shfl_xor_sync(0xffffffffu, s, o);
        const float inv = 1.f / s;
        sp[i * 50 + lane] = e0 * inv;
        if (lane + 32 < NTOK) sp[i * 50 + lane + 32] = e1 * inv;
    }
    __syncthreads();

    for (int e = tid; e < NTOK * 32; e += 256) {
        const int i = e >> 5, d = e & 31;
        float acc = 0.f;
#pragma unroll
        for (int j = 0; j < NTOK; j++) acc += sp[i * 50 + j] * sv[j * 33 + d];
        out[((size_t)b * NTOK + i) * CDIM + h * 32 + d] = acc;
    }
}

// ---------------------------------------------------------------------------
// Launch
// ---------------------------------------------------------------------------
extern "C" void kernel_launch(void* const* d_in, const int* in_sizes, int n_in,
                              void* d_out, int out_size)
{
    const float* x      = (const float*)d_in[0];
    const float* qkv_w  = (const float*)d_in[1];
    const float* qkv_b  = (const float*)d_in[2];
    const float* rpb    = (const float*)d_in[3];
    const float* proj_w = (const float*)d_in[4];
    const float* proj_b = (const float*)d_in[5];
    float* out = (float*)d_out;

    float* qkv = nullptr;
    float* att = nullptr;
    cudaGetSymbolAddress((void**)&qkv, g_qkv);
    cudaGetSymbolAddress((void**)&att, g_att);

    // 1) QKV GEMM: [200704,256] @ [256,768] + bias
    {
        dim3 grid(768 / 128, MROWS / 128);
        sgemm_bias_kernel<<<grid, 256>>>(x, qkv_w, qkv_b, qkv, MROWS, 768, CDIM);
    }
    // 2) Windowed attention (per window, per head)
    {
        dim3 grid(BWIN, NHEAD);
        window_attn_kernel<<<grid, 256>>>(qkv, rpb, att);
    }
    // 3) Projection GEMM: [200704,256] @ [256,256] + bias
    {
        dim3 grid(CDIM / 128, MROWS / 128);
        sgemm_bias_kernel<<<grid, 256>>>(att, proj_w, proj_b, out, MROWS, CDIM, CDIM);
    }
}

// round 2
// speedup vs baseline: 1.6367x; 1.6367x over previous
#include <cuda_runtime.h>
#include <cuda_bf16.h>
#include <cstdint>

// Problem constants (fixed by setup_inputs)
#define BWIN   4096          // number of windows
#define NTOK   49            // tokens per window (7x7)
#define CDIM   256           // channels
#define NHEAD  8
#define DHEAD  32
#define MROWS  (BWIN * NTOK) // 200704

// ---------------------------------------------------------------------------
// Scratch (device globals; no runtime allocation allowed)
// ---------------------------------------------------------------------------
__device__ float g_qkv[(size_t)MROWS * 768];   // [B*N, 3C]
__device__ float g_att[(size_t)MROWS * CDIM];  // [B*N, C]

// ---------------------------------------------------------------------------
// tf32 tensor-core GEMM with bias: C[M,N] = A[M,K] @ B[K,N] + bias[N]
// BM=128, BN=128, BK=16, 128 threads (4 warps, warp tile 64x64),
// mma.sync.aligned.m16n8k8.row.col.f32.tf32.tf32.f32, double-buffered smem.
// Fragments stored frag-major with stride-33 padding:
//   As[buf][(((kc*8 + mt)*4 + reg)*33) + lane]
//   Bs[buf][(((kc*16 + nt)*2 + reg)*33) + lane]
// so compute-side LDS.32 loads are perfectly conflict-free.
// Requires M%128==0, N%128==0, K%16==0.
// ---------------------------------------------------------------------------
__device__ __forceinline__ uint32_t f2tf32(float f) {
    uint32_t u;
    asm("cvt.rna.tf32.f32 %0, %1;" : "=r"(u) : "f"(f));
    return u;
}

__global__ __launch_bounds__(128, 2)
void tf32_gemm_bias(const float* __restrict__ A,
                    const float* __restrict__ B,
                    const float* __restrict__ bias,
                    float* __restrict__ C,
                    int M, int N, int K)
{
    constexpr int BM = 128, BN = 128, BK = 16;
    constexpr int ASZ = 2 * 8 * 4 * 33;   // 2112 floats per buffer
    constexpr int BSZ = 2 * 16 * 2 * 33;  // 2112 floats per buffer
    __shared__ uint32_t As[2][ASZ];
    __shared__ uint32_t Bs[2][BSZ];

    const int tid  = threadIdx.x;
    const int lane = tid & 31;
    const int warp = tid >> 5;            // 0..3
    const int wm   = warp & 1;            // m half
    const int wn   = warp >> 1;           // n half

    const int bm = blockIdx.y * BM;
    const int bn = blockIdx.x * BN;

    // --- global load mappings -------------------------------------------
    // A: thread q-th load: row = q*32 + (tid>>2), k = (tid&3)*4 .. +3
    const int a_r = tid >> 2;            // 0..31
    const int a_kb = (tid & 3) * 4;      // 0,4,8,12
    // precomputed A scatter targets (tig == element index e)
    const int a_kc = a_kb >> 3;          // k chunk 0/1
    const int a_kh = (a_kb >> 2) & 1;    // k half 0/1
    // B: thread q-th load: k = q*4 + (tid>>5), n = (tid&31)*4 .. +3
    const int b_kq = tid >> 5;           // 0..3
    const int b_nb = (tid & 31) * 4;     // 0..124

    const float* Ag = A + (size_t)bm * K;
    const float* Bg = B + bn;

    float acc[4][8][4];
#pragma unroll
    for (int i = 0; i < 4; i++)
#pragma unroll
        for (int j = 0; j < 8; j++)
#pragma unroll
            for (int r = 0; r < 4; r++) acc[i][j][r] = 0.f;

    const int NT = K / BK;

    // --- tile loader (gmem -> regs) --------------------------------------
    float4 va[4], vb[4];
    auto load_gmem = [&](int k0) {
#pragma unroll
        for (int q = 0; q < 4; q++) {
            const int m_ = q * 32 + a_r;
            va[q] = *(const float4*)(Ag + (size_t)m_ * K + k0 + a_kb);
        }
#pragma unroll
        for (int q = 0; q < 4; q++) {
            const int k_ = q * 4 + b_kq;
            vb[q] = *(const float4*)(Bg + (size_t)(k0 + k_) * N + b_nb);
        }
    };

    // --- regs -> smem (frag layout, cvt to tf32) --------------------------
    auto store_smem = [&](int buf) {
#pragma unroll
        for (int q = 0; q < 4; q++) {
            const int m_ = q * 32 + a_r;
            const int mt = m_ >> 4;
            const int mm = m_ & 15;
            const int rh = mm >> 3;
            const int g  = mm & 7;
            const int reg = rh + 2 * a_kh;
            const int base = ((a_kc * 8 + mt) * 4 + reg) * 33 + g * 4;
            const float* v = (const float*)&va[q];
#pragma unroll
            for (int e = 0; e < 4; e++)
                As[buf][base + e] = f2tf32(v[e]);
        }
#pragma unroll
        for (int q = 0; q < 4; q++) {
            const int k_ = q * 4 + b_kq;
            const int kc = k_ >> 3;
            const int kb = k_ & 7;
            const int tig = kb & 3;
            const int reg = kb >> 2;
            const float* v = (const float*)&vb[q];
#pragma unroll
            for (int e = 0; e < 4; e++) {
                const int n_ = b_nb + e;
                const int nt = n_ >> 3;
                const int g  = n_ & 7;
                Bs[buf][((kc * 16 + nt) * 2 + reg) * 33 + g * 4 + tig] = f2tf32(v[e]);
            }
        }
    };

    // --- compute one buffer -----------------------------------------------
    auto compute = [&](int buf) {
#pragma unroll
        for (int kc = 0; kc < 2; kc++) {
            uint32_t af[4][4];
#pragma unroll
            for (int mt = 0; mt < 4; mt++) {
                const int base = ((kc * 8 + (wm * 4 + mt)) * 4) * 33 + lane;
#pragma unroll
                for (int r = 0; r < 4; r++) af[mt][r] = As[buf][base + r * 33];
            }
            uint32_t bf[8][2];
#pragma unroll
            for (int nt = 0; nt < 8; nt++) {
                const int base = ((kc * 16 + (wn * 8 + nt)) * 2) * 33 + lane;
                bf[nt][0] = Bs[buf][base];
                bf[nt][1] = Bs[buf][base + 33];
            }
#pragma unroll
            for (int mt = 0; mt < 4; mt++) {
#pragma unroll
                for (int nt = 0; nt < 8; nt++) {
                    asm volatile(
                        "mma.sync.aligned.m16n8k8.row.col.f32.tf32.tf32.f32 "
                        "{%0,%1,%2,%3}, {%4,%5,%6,%7}, {%8,%9}, {%0,%1,%2,%3};"
                        : "+f"(acc[mt][nt][0]), "+f"(acc[mt][nt][1]),
                          "+f"(acc[mt][nt][2]), "+f"(acc[mt][nt][3])
                        : "r"(af[mt][0]), "r"(af[mt][1]), "r"(af[mt][2]), "r"(af[mt][3]),
                          "r"(bf[nt][0]), "r"(bf[nt][1]));
                }
            }
        }
    };

    // --- main loop (double-buffered) ---------------------------------------
    load_gmem(0);
    store_smem(0);
    __syncthreads();

    int buf = 0;
    for (int t = 0; t < NT; t++) {
        if (t + 1 < NT) load_gmem((t + 1) * BK);
        compute(buf);
        if (t + 1 < NT) store_smem(buf ^ 1);
        __syncthreads();
        buf ^= 1;
    }

    // --- epilogue: bias + store --------------------------------------------
    const int g   = lane >> 2;
    const int tig = lane & 3;
#pragma unroll
    for (int mt = 0; mt < 4; mt++) {
        const int r0 = bm + wm * 64 + mt * 16 + g;
#pragma unroll
        for (int nt = 0; nt < 8; nt++) {
            const int col = bn + wn * 64 + nt * 8 + tig * 2;
            const float b0 = __ldg(bias + col);
            const float b1 = __ldg(bias + col + 1);
            float2 v0 = make_float2(acc[mt][nt][0] + b0, acc[mt][nt][1] + b1);
            float2 v1 = make_float2(acc[mt][nt][2] + b0, acc[mt][nt][3] + b1);
            *(float2*)(C + (size_t)r0 * N + col)       = v0;
            *(float2*)(C + (size_t)(r0 + 8) * N + col) = v1;
        }
    }
}

// ---------------------------------------------------------------------------
// Fused windowed attention: one block per (window, head).
// qkv layout per row (768): [q(8 heads x 32) | k(...) | v(...)]
// ---------------------------------------------------------------------------
__global__ __launch_bounds__(256)
void window_attn_kernel(const float* __restrict__ qkv,
                        const float* __restrict__ rpb,   // [169, 8]
                        float* __restrict__ out)
{
    const int b = blockIdx.x;
    const int h = blockIdx.y;

    __shared__ float sq[NTOK * 33];
    __shared__ float sk[NTOK * 33];
    __shared__ float sv[NTOK * 33];
    __shared__ float sp[NTOK * 50];
    __shared__ float srpb[169];

    const int tid = threadIdx.x;
    const float* base = qkv + (size_t)b * NTOK * 768;

    for (int e = tid; e < NTOK * 32; e += 256) {
        const int n = e >> 5, d = e & 31;
        const float* r = base + (size_t)n * 768 + h * 32 + d;
        sq[n * 33 + d] = r[0];
        sk[n * 33 + d] = r[256];
        sv[n * 33 + d] = r[512];
    }
    for (int e = tid; e < 169; e += 256) srpb[e] = rpb[e * 8 + h];
    __syncthreads();

    const float scale = 0.17677669529663687f;  // 32^-0.5
    for (int e = tid; e < NTOK * NTOK; e += 256) {
        const int i = e / NTOK, j = e - i * NTOK;
        float s = 0.f;
#pragma unroll
        for (int d = 0; d < 32; d++) s += sq[i * 33 + d] * sk[j * 33 + d];
        const int xi = i / 7, yi = i - xi * 7;
        const int xj = j / 7, yj = j - xj * 7;
        const int idx = (xi - xj + 6) * 13 + (yi - yj + 6);
        sp[i * 50 + j] = s * scale + srpb[idx];
    }
    __syncthreads();

    // Row softmax: one warp per row
    const int warp = tid >> 5, lane = tid & 31;
    for (int i = warp; i < NTOK; i += 8) {
        float v0 = sp[i * 50 + lane];
        float v1 = (lane + 32 < NTOK) ? sp[i * 50 + lane + 32] : -1e30f;
        float m = fmaxf(v0, v1);
#pragma unroll
        for (int o = 16; o > 0; o >>= 1) m = fmaxf(m, __shfl_xor_sync(0xffffffffu, m, o));
        const float e0 = __expf(v0 - m);
        const float e1 = (lane + 32 < NTOK) ? __expf(v1 - m) : 0.f;
        float s = e0 + e1;
#pragma unroll
        for (int o = 16; o > 0; o >>= 1) s += __shfl_xor_sync(0xffffffffu, s, o);
        const float inv = 1.f / s;
        sp[i * 50 + lane] = e0 * inv;
        if (lane + 32 < NTOK) sp[i * 50 + lane + 32] = e1 * inv;
    }
    __syncthreads();

    for (int e = tid; e < NTOK * 32; e += 256) {
        const int i = e >> 5, d = e & 31;
        float acc = 0.f;
#pragma unroll
        for (int j = 0; j < NTOK; j++) acc += sp[i * 50 + j] * sv[j * 33 + d];
        out[((size_t)b * NTOK + i) * CDIM + h * 32 + d] = acc;
    }
}

// ---------------------------------------------------------------------------
// Launch
// ---------------------------------------------------------------------------
extern "C" void kernel_launch(void* const* d_in, const int* in_sizes, int n_in,
                              void* d_out, int out_size)
{
    const float* x      = (const float*)d_in[0];
    const float* qkv_w  = (const float*)d_in[1];
    const float* qkv_b  = (const float*)d_in[2];
    const float* rpb    = (const float*)d_in[3];
    const float* proj_w = (const float*)d_in[4];
    const float* proj_b = (const float*)d_in[5];
    float* out = (float*)d_out;

    float* qkv = nullptr;
    float* att = nullptr;
    cudaGetSymbolAddress((void**)&qkv, g_qkv);
    cudaGetSymbolAddress((void**)&att, g_att);

    // 1) QKV GEMM: [200704,256] @ [256,768] + bias  (tf32 tensor cores)
    {
        dim3 grid(768 / 128, MROWS / 128);
        tf32_gemm_bias<<<grid, 128>>>(x, qkv_w, qkv_b, qkv, MROWS, 768, CDIM);
    }
    // 2) Windowed attention (per window, per head)
    {
        dim3 grid(BWIN, NHEAD);
        window_attn_kernel<<<grid, 256>>>(qkv, rpb, att);
    }
    // 3) Projection GEMM: [200704,256] @ [256,256] + bias  (tf32 tensor cores)
    {
        dim3 grid(CDIM / 128, MROWS / 128);
        tf32_gemm_bias<<<grid, 128>>>(att, proj_w, proj_b, out, MROWS, CDIM, CDIM);
    }
}

// round 3
// speedup vs baseline: 3.0119x; 1.8402x over previous
#include <cuda_runtime.h>
#include <cuda_bf16.h>
#include <cstdint>

// Problem constants (fixed by setup_inputs)
#define BWIN   4096          // number of windows
#define NTOK   49            // tokens per window (7x7)
#define CDIM   256           // channels
#define NHEAD  8
#define DHEAD  32
#define MROWS  (BWIN * NTOK) // 200704

// ---------------------------------------------------------------------------
// Scratch (device globals; no runtime allocation allowed)
// ---------------------------------------------------------------------------
__device__ float g_qkv[(size_t)MROWS * 768];   // [B*N, 3C]
__device__ float g_att[(size_t)MROWS * CDIM];  // [B*N, C]

__device__ __forceinline__ uint32_t f2tf32(float f) {
    uint32_t u;
    asm("cvt.rna.tf32.f32 %0, %1;" : "=r"(u) : "f"(f));
    return u;
}

// ---------------------------------------------------------------------------
// tf32 tensor-core GEMM with bias: C[M,N] = A[M,K] @ B[K,N] + bias[N]
// (unchanged from round 2)
// ---------------------------------------------------------------------------
__global__ __launch_bounds__(128, 2)
void tf32_gemm_bias(const float* __restrict__ A,
                    const float* __restrict__ B,
                    const float* __restrict__ bias,
                    float* __restrict__ C,
                    int M, int N, int K)
{
    constexpr int BM = 128, BN = 128, BK = 16;
    constexpr int ASZ = 2 * 8 * 4 * 33;
    constexpr int BSZ = 2 * 16 * 2 * 33;
    __shared__ uint32_t As[2][ASZ];
    __shared__ uint32_t Bs[2][BSZ];

    const int tid  = threadIdx.x;
    const int lane = tid & 31;
    const int warp = tid >> 5;
    const int wm   = warp & 1;
    const int wn   = warp >> 1;

    const int bm = blockIdx.y * BM;
    const int bn = blockIdx.x * BN;

    const int a_r  = tid >> 2;
    const int a_kb = (tid & 3) * 4;
    const int a_kc = a_kb >> 3;
    const int a_kh = (a_kb >> 2) & 1;
    const int b_kq = tid >> 5;
    const int b_nb = (tid & 31) * 4;

    const float* Ag = A + (size_t)bm * K;
    const float* Bg = B + bn;

    float acc[4][8][4];
#pragma unroll
    for (int i = 0; i < 4; i++)
#pragma unroll
        for (int j = 0; j < 8; j++)
#pragma unroll
            for (int r = 0; r < 4; r++) acc[i][j][r] = 0.f;

    const int NT = K / BK;

    float4 va[4], vb[4];
    auto load_gmem = [&](int k0) {
#pragma unroll
        for (int q = 0; q < 4; q++) {
            const int m_ = q * 32 + a_r;
            va[q] = *(const float4*)(Ag + (size_t)m_ * K + k0 + a_kb);
        }
#pragma unroll
        for (int q = 0; q < 4; q++) {
            const int k_ = q * 4 + b_kq;
            vb[q] = *(const float4*)(Bg + (size_t)(k0 + k_) * N + b_nb);
        }
    };

    auto store_smem = [&](int buf) {
#pragma unroll
        for (int q = 0; q < 4; q++) {
            const int m_ = q * 32 + a_r;
            const int mt = m_ >> 4;
            const int mm = m_ & 15;
            const int rh = mm >> 3;
            const int g  = mm & 7;
            const int reg = rh + 2 * a_kh;
            const int base = ((a_kc * 8 + mt) * 4 + reg) * 33 + g * 4;
            const float* v = (const float*)&va[q];
#pragma unroll
            for (int e = 0; e < 4; e++)
                As[buf][base + e] = f2tf32(v[e]);
        }
#pragma unroll
        for (int q = 0; q < 4; q++) {
            const int k_ = q * 4 + b_kq;
            const int kc = k_ >> 3;
            const int kb = k_ & 7;
            const int tig = kb & 3;
            const int reg = kb >> 2;
            const float* v = (const float*)&vb[q];
#pragma unroll
            for (int e = 0; e < 4; e++) {
                const int n_ = b_nb + e;
                const int nt = n_ >> 3;
                const int g  = n_ & 7;
                Bs[buf][((kc * 16 + nt) * 2 + reg) * 33 + g * 4 + tig] = f2tf32(v[e]);
            }
        }
    };

    auto compute = [&](int buf) {
#pragma unroll
        for (int kc = 0; kc < 2; kc++) {
            uint32_t af[4][4];
#pragma unroll
            for (int mt = 0; mt < 4; mt++) {
                const int base = ((kc * 8 + (wm * 4 + mt)) * 4) * 33 + lane;
#pragma unroll
                for (int r = 0; r < 4; r++) af[mt][r] = As[buf][base + r * 33];
            }
            uint32_t bf[8][2];
#pragma unroll
            for (int nt = 0; nt < 8; nt++) {
                const int base = ((kc * 16 + (wn * 8 + nt)) * 2) * 33 + lane;
                bf[nt][0] = Bs[buf][base];
                bf[nt][1] = Bs[buf][base + 33];
            }
#pragma unroll
            for (int mt = 0; mt < 4; mt++) {
#pragma unroll
                for (int nt = 0; nt < 8; nt++) {
                    asm volatile(
                        "mma.sync.aligned.m16n8k8.row.col.f32.tf32.tf32.f32 "
                        "{%0,%1,%2,%3}, {%4,%5,%6,%7}, {%8,%9}, {%0,%1,%2,%3};"
                        : "+f"(acc[mt][nt][0]), "+f"(acc[mt][nt][1]),
                          "+f"(acc[mt][nt][2]), "+f"(acc[mt][nt][3])
                        : "r"(af[mt][0]), "r"(af[mt][1]), "r"(af[mt][2]), "r"(af[mt][3]),
                          "r"(bf[nt][0]), "r"(bf[nt][1]));
                }
            }
        }
    };

    load_gmem(0);
    store_smem(0);
    __syncthreads();

    int buf = 0;
    for (int t = 0; t < NT; t++) {
        if (t + 1 < NT) load_gmem((t + 1) * BK);
        compute(buf);
        if (t + 1 < NT) store_smem(buf ^ 1);
        __syncthreads();
        buf ^= 1;
    }

    const int g   = lane >> 2;
    const int tig = lane & 3;
#pragma unroll
    for (int mt = 0; mt < 4; mt++) {
        const int r0 = bm + wm * 64 + mt * 16 + g;
#pragma unroll
        for (int nt = 0; nt < 8; nt++) {
            const int col = bn + wn * 64 + nt * 8 + tig * 2;
            const float b0 = __ldg(bias + col);
            const float b1 = __ldg(bias + col + 1);
            float2 v0 = make_float2(acc[mt][nt][0] + b0, acc[mt][nt][1] + b1);
            float2 v1 = make_float2(acc[mt][nt][2] + b0, acc[mt][nt][3] + b1);
            *(float2*)(C + (size_t)r0 * N + col)       = v0;
            *(float2*)(C + (size_t)(r0 + 8) * N + col) = v1;
        }
    }
}

// ---------------------------------------------------------------------------
// Tensor-core windowed attention: one block per (window, head), 4 warps.
// Padded problem: 64 (Q rows) x 56 (K/V rows) x 32 (head dim).
// Warp w owns Q rows [w*16, w*16+16). QK^T and AV both via m16n8k8 tf32 mma.
// Softmax in fragments (shfl over the 4-lane row group); exp(S) bounced
// through smem; normalization folded into the output store.
// Smem strides chosen for conflict-free fragment LDS:
//   sq/sk stride 36 (bank=4r+c unique), sv stride 40 (bank=8k+n unique),
//   sp stride 60 (bank=28r+c unique).
// ---------------------------------------------------------------------------
__global__ __launch_bounds__(128)
void window_attn_tc(const float* __restrict__ qkv,
                    const float* __restrict__ rpb,   // [169, 8]
                    float* __restrict__ out)
{
    __shared__ float sq[64 * 36];
    __shared__ float sk[56 * 36];
    __shared__ float sv[56 * 40];
    __shared__ float sp[64 * 60];
    __shared__ float srpb[169];

    const int b = blockIdx.x;
    const int h = blockIdx.y;
    const int tid  = threadIdx.x;
    const int lane = tid & 31;
    const int warp = tid >> 5;
    const int g = lane >> 2;     // row-in-group
    const int t = lane & 3;      // col-in-group

    const float scale = 0.17677669529663687f;  // 32^-0.5
    const float* base = qkv + (size_t)b * NTOK * 768 + h * 32;

    // ---- load q (scaled), k, v into smem as tf32; clamp padded rows ------
#pragma unroll
    for (int it = 0; it < 4; it++) {             // q: 64 rows x 8 float4
        const int e = tid + it * 128;            // 0..511
        const int row = e >> 3, c4 = e & 7;
        const int sr = row < NTOK ? row : NTOK - 1;
        float4 v = *(const float4*)(base + (size_t)sr * 768 + c4 * 4);
        uint32_t* d = (uint32_t*)&sq[row * 36 + c4 * 4];
        d[0] = f2tf32(v.x * scale); d[1] = f2tf32(v.y * scale);
        d[2] = f2tf32(v.z * scale); d[3] = f2tf32(v.w * scale);
    }
#pragma unroll
    for (int it = 0; it < 4; it++) {             // k: 56 rows x 8 float4
        const int e = tid + it * 128;
        if (e < 448) {
            const int row = e >> 3, c4 = e & 7;
            const int sr = row < NTOK ? row : NTOK - 1;
            float4 v = *(const float4*)(base + (size_t)sr * 768 + 256 + c4 * 4);
            uint32_t* d = (uint32_t*)&sk[row * 36 + c4 * 4];
            d[0] = f2tf32(v.x); d[1] = f2tf32(v.y);
            d[2] = f2tf32(v.z); d[3] = f2tf32(v.w);
        }
    }
#pragma unroll
    for (int it = 0; it < 4; it++) {             // v: 56 rows x 8 float4
        const int e = tid + it * 128;
        if (e < 448) {
            const int row = e >> 3, c4 = e & 7;
            const int sr = row < NTOK ? row : NTOK - 1;
            float4 v = *(const float4*)(base + (size_t)sr * 768 + 512 + c4 * 4);
            uint32_t* d = (uint32_t*)&sv[row * 40 + c4 * 4];
            d[0] = f2tf32(v.x); d[1] = f2tf32(v.y);
            d[2] = f2tf32(v.z); d[3] = f2tf32(v.w);
        }
    }
    for (int e = tid; e < 169; e += 128) srpb[e] = rpb[e * 8 + h];
    __syncthreads();

    // ---- QK^T: warp computes S[16 x 56] ------------------------------------
    const int mtb = warp * 16;
    float sc[7][4];
#pragma unroll
    for (int nt = 0; nt < 7; nt++)
#pragma unroll
        for (int r = 0; r < 4; r++) sc[nt][r] = 0.f;

#pragma unroll
    for (int ko = 0; ko < 4; ko++) {
        uint32_t a0, a1, a2, a3;
        {
            const float* p0 = &sq[(mtb + g) * 36 + ko * 8 + t];
            const float* p1 = &sq[(mtb + g + 8) * 36 + ko * 8 + t];
            a0 = __float_as_uint(p0[0]); a2 = __float_as_uint(p0[4]);
            a1 = __float_as_uint(p1[0]); a3 = __float_as_uint(p1[4]);
        }
#pragma unroll
        for (int nt = 0; nt < 7; nt++) {
            const float* pb = &sk[(nt * 8 + g) * 36 + ko * 8 + t];
            uint32_t b0 = __float_as_uint(pb[0]);
            uint32_t b1 = __float_as_uint(pb[4]);
            asm volatile(
                "mma.sync.aligned.m16n8k8.row.col.f32.tf32.tf32.f32 "
                "{%0,%1,%2,%3}, {%4,%5,%6,%7}, {%8,%9}, {%0,%1,%2,%3};"
                : "+f"(sc[nt][0]), "+f"(sc[nt][1]), "+f"(sc[nt][2]), "+f"(sc[nt][3])
                : "r"(a0), "r"(a1), "r"(a2), "r"(a3), "r"(b0), "r"(b1));
        }
    }

    // ---- bias + mask + row softmax (in fragments) ---------------------------
    const int i0 = mtb + g, i1 = i0 + 8;
    const int xi0 = i0 / 7, yi0 = i0 - xi0 * 7;
    const int xi1 = i1 / 7, yi1 = i1 - xi1 * 7;
    const bool v0 = i0 < NTOK, v1 = i1 < NTOK;

    float m0 = -1e30f, m1 = -1e30f;
#pragma unroll
    for (int nt = 0; nt < 7; nt++) {
#pragma unroll
        for (int e = 0; e < 2; e++) {
            const int j = nt * 8 + 2 * t + e;
            const bool jv = j < NTOK;
            const int xj = j / 7, yj = j - xj * 7;
            if (v0 && jv)
                sc[nt][e] += srpb[(xi0 - xj + 6) * 13 + (yi0 - yj + 6)];
            else
                sc[nt][e] = -1e30f;
            if (v1 && jv)
                sc[nt][2 + e] += srpb[(xi1 - xj + 6) * 13 + (yi1 - yj + 6)];
            else
                sc[nt][2 + e] = -1e30f;
            m0 = fmaxf(m0, sc[nt][e]);
            m1 = fmaxf(m1, sc[nt][2 + e]);
        }
    }
    m0 = fmaxf(m0, __shfl_xor_sync(0xffffffffu, m0, 1));
    m0 = fmaxf(m0, __shfl_xor_sync(0xffffffffu, m0, 2));
    m1 = fmaxf(m1, __shfl_xor_sync(0xffffffffu, m1, 1));
    m1 = fmaxf(m1, __shfl_xor_sync(0xffffffffu, m1, 2));

    float s0 = 0.f, s1 = 0.f;
#pragma unroll
    for (int nt = 0; nt < 7; nt++) {
#pragma unroll
        for (int e = 0; e < 2; e++) {
            float p0 = __expf(sc[nt][e] - m0);
            float p1 = __expf(sc[nt][2 + e] - m1);
            sc[nt][e] = p0;  sc[nt][2 + e] = p1;
            s0 += p0;  s1 += p1;
        }
    }
    s0 += __shfl_xor_sync(0xffffffffu, s0, 1);
    s0 += __shfl_xor_sync(0xffffffffu, s0, 2);
    s1 += __shfl_xor_sync(0xffffffffu, s1, 1);
    s1 += __shfl_xor_sync(0xffffffffu, s1, 2);
    const float inv0 = 1.f / s0, inv1 = 1.f / s1;

    // write exp(S) (unnormalized, tf32) to smem for AV A-fragments
#pragma unroll
    for (int nt = 0; nt < 7; nt++) {
        const int j = nt * 8 + 2 * t;
        uint32_t* d0 = (uint32_t*)&sp[i0 * 60 + j];
        uint32_t* d1 = (uint32_t*)&sp[i1 * 60 + j];
        d0[0] = f2tf32(sc[nt][0]); d0[1] = f2tf32(sc[nt][1]);
        d1[0] = f2tf32(sc[nt][2]); d1[1] = f2tf32(sc[nt][3]);
    }
    __syncwarp();

    // ---- AV: O[16 x 32] -----------------------------------------------------
    float ov[4][4];
#pragma unroll
    for (int nt = 0; nt < 4; nt++)
#pragma unroll
        for (int r = 0; r < 4; r++) ov[nt][r] = 0.f;

#pragma unroll
    for (int ko = 0; ko < 7; ko++) {
        uint32_t a0, a1, a2, a3;
        {
            const float* p0 = &sp[(mtb + g) * 60 + ko * 8 + t];
            const float* p1 = &sp[(mtb + g + 8) * 60 + ko * 8 + t];
            a0 = __float_as_uint(p0[0]); a2 = __float_as_uint(p0[4]);
            a1 = __float_as_uint(p1[0]); a3 = __float_as_uint(p1[4]);
        }
#pragma unroll
        for (int nt = 0; nt < 4; nt++) {
            const float* pb = &sv[(ko * 8 + t) * 40 + nt * 8 + g];
            uint32_t b0 = __float_as_uint(pb[0]);
            uint32_t b1 = __float_as_uint(pb[4 * 40]);
            asm volatile(
                "mma.sync.aligned.m16n8k8.row.col.f32.tf32.tf32.f32 "
                "{%0,%1,%2,%3}, {%4,%5,%6,%7}, {%8,%9}, {%0,%1,%2,%3};"
                : "+f"(ov[nt][0]), "+f"(ov[nt][1]), "+f"(ov[nt][2]), "+f"(ov[nt][3])
                : "r"(a0), "r"(a1), "r"(a2), "r"(a3), "r"(b0), "r"(b1));
        }
    }

    // ---- output: normalize and store ---------------------------------------
#pragma unroll
    for (int nt = 0; nt < 4; nt++) {
        const int col = h * 32 + nt * 8 + 2 * t;
        if (v0) {
            float2 w = make_float2(ov[nt][0] * inv0, ov[nt][1] * inv0);
            *(float2*)(out + ((size_t)b * NTOK + i0) * CDIM + col) = w;
        }
        if (v1) {
            float2 w = make_float2(ov[nt][2] * inv1, ov[nt][3] * inv1);
            *(float2*)(out + ((size_t)b * NTOK + i1) * CDIM + col) = w;
        }
    }
}

// ---------------------------------------------------------------------------
// Launch
// ---------------------------------------------------------------------------
extern "C" void kernel_launch(void* const* d_in, const int* in_sizes, int n_in,
                              void* d_out, int out_size)
{
    const float* x      = (const float*)d_in[0];
    const float* qkv_w  = (const float*)d_in[1];
    const float* qkv_b  = (const float*)d_in[2];
    const float* rpb    = (const float*)d_in[3];
    const float* proj_w = (const float*)d_in[4];
    const float* proj_b = (const float*)d_in[5];
    float* out = (float*)d_out;

    float* qkv = nullptr;
    float* att = nullptr;
    cudaGetSymbolAddress((void**)&qkv, g_qkv);
    cudaGetSymbolAddress((void**)&att, g_att);

    // 1) QKV GEMM: [200704,256] @ [256,768] + bias  (tf32 tensor cores)
    {
        dim3 grid(768 / 128, MROWS / 128);
        tf32_gemm_bias<<<grid, 128>>>(x, qkv_w, qkv_b, qkv, MROWS, 768, CDIM);
    }
    // 2) Windowed attention (tensor cores, per window-head)
    {
        dim3 grid(BWIN, NHEAD);
        window_attn_tc<<<grid, 128>>>(qkv, rpb, att);
    }
    // 3) Projection GEMM: [200704,256] @ [256,256] + bias  (tf32 tensor cores)
    {
        dim3 grid(CDIM / 128, MROWS / 128);
        tf32_gemm_bias<<<grid, 128>>>(att, proj_w, proj_b, out, MROWS, CDIM, CDIM);
    }
}

// round 4
// speedup vs baseline: 3.5258x; 1.1706x over previous
#include <cuda_runtime.h>
#include <cuda_bf16.h>
#include <cuda_fp16.h>
#include <cstdint>

// Problem constants (fixed by setup_inputs)
#define BWIN   4096          // number of windows
#define NTOK   49            // tokens per window (7x7)
#define CDIM   256           // channels
#define NHEAD  8
#define DHEAD  32
#define MROWS  (BWIN * NTOK) // 200704

// ---------------------------------------------------------------------------
// Scratch (device globals; no runtime allocation allowed)
// ---------------------------------------------------------------------------
__device__ float g_qkv[(size_t)MROWS * 768];   // [B*N, 3C]
__device__ float g_att[(size_t)MROWS * CDIM];  // [B*N, C]

__device__ __forceinline__ uint32_t f2tf32(float f) {
    uint32_t u;
    asm("cvt.rna.tf32.f32 %0, %1;" : "=r"(u) : "f"(f));
    return u;
}
__device__ __forceinline__ uint32_t pack_h2(float a, float b) {
    __half2 h = __floats2half2_rn(a, b);
    return *(uint32_t*)&h;
}

// ---------------------------------------------------------------------------
// fp16 tensor-core GEMM with bias: C[M,N] = A[M,K] @ B[K,N] + bias[N]
// BM=128, BN=128, BK=16, 128 threads (4 warps, warp tile 64x64),
// mma.sync.aligned.m16n8k16.row.col.f32.f16.f16.f32, double-buffered smem.
// Fragments stored frag-major as half2 words:
//   As[(mt*4 + reg)*40 + lane]   (stride 40 -> A STS.64 conflict-free,
//                                 compute LDS.32 conflict-free)
//   Bs[(nt*2 + reg)*33 + lane]   (compute LDS.32 conflict-free)
// Requires M%128==0, N%128==0, K%16==0.
// ---------------------------------------------------------------------------
__global__ __launch_bounds__(128, 2)
void h16_gemm_bias(const float* __restrict__ A,
                   const float* __restrict__ B,
                   const float* __restrict__ bias,
                   float* __restrict__ C,
                   int M, int N, int K)
{
    constexpr int BM = 128, BN = 128, BK = 16;
    constexpr int ASZ = 8 * 4 * 40;   // 1280 words per buffer
    constexpr int BSZ = 16 * 2 * 33;  // 1056 words per buffer
    __shared__ uint32_t As[2][ASZ];
    __shared__ uint32_t Bs[2][BSZ];

    const int tid  = threadIdx.x;
    const int lane = tid & 31;
    const int warp = tid >> 5;
    const int wm   = warp & 1;
    const int wn   = warp >> 1;

    const int bm = blockIdx.y * BM;
    const int bn = blockIdx.x * BN;

    // A global-load / frag-store mapping
    const int a_r   = tid >> 2;            // 0..31 (m within 32-row group)
    const int a_k   = (tid & 3) * 4;       // 0,4,8,12
    const int a_t   = (a_k & 7) >> 1;      // 0 or 2
    const int a_rb  = (a_k >> 3) * 2;      // 0 or 2
    const int a_rh  = (a_r >> 3) & 1;
    const int a_g   = a_r & 7;
    // B global-load / frag-store mapping (loads k-pairs so half2 packs along K)
    const int b_n0  = (tid & 63) * 2;      // 0..126
    const int b_kb  = (tid >> 6) * 2;      // 0 or 2
    const int b_nt  = b_n0 >> 3;
    const int b_g   = b_n0 & 7;

    const float* Ag = A + (size_t)bm * K;
    const float* Bg = B + bn;

    float acc[4][8][4];
#pragma unroll
    for (int i = 0; i < 4; i++)
#pragma unroll
        for (int j = 0; j < 8; j++)
#pragma unroll
            for (int r = 0; r < 4; r++) acc[i][j][r] = 0.f;

    const int NT = K / BK;

    float4 va[4];
    float2 vb0[4], vb1[4];
    auto load_gmem = [&](int k0) {
#pragma unroll
        for (int q = 0; q < 4; q++) {
            const int m_ = q * 32 + a_r;
            va[q] = *(const float4*)(Ag + (size_t)m_ * K + k0 + a_k);
        }
#pragma unroll
        for (int q = 0; q < 4; q++) {
            const int k_ = q * 4 + b_kb;
            vb0[q] = *(const float2*)(Bg + (size_t)(k0 + k_) * N + b_n0);
            vb1[q] = *(const float2*)(Bg + (size_t)(k0 + k_ + 1) * N + b_n0);
        }
    };

    auto store_smem = [&](int buf) {
#pragma unroll
        for (int q = 0; q < 4; q++) {
            const int mt = 2 * q + (a_r >> 4);
            const int addr = (mt * 4 + a_rh + a_rb) * 40 + a_g * 4 + a_t;
            uint2 w;
            w.x = pack_h2(va[q].x, va[q].y);
            w.y = pack_h2(va[q].z, va[q].w);
            *(uint2*)&As[buf][addr] = w;   // addr even -> 8B aligned
        }
#pragma unroll
        for (int q = 0; q < 4; q++) {
            const int k_  = q * 4 + b_kb;
            const int t   = (k_ & 7) >> 1;
            const int reg = k_ >> 3;
            const int base = (b_nt * 2 + reg) * 33 + b_g * 4 + t;
            Bs[buf][base]     = pack_h2(vb0[q].x, vb1[q].x);
            Bs[buf][base + 4] = pack_h2(vb0[q].y, vb1[q].y);
        }
    };

    auto compute = [&](int buf) {
        uint32_t af[4][4];
#pragma unroll
        for (int mt = 0; mt < 4; mt++) {
            const int base = ((wm * 4 + mt) * 4) * 40 + lane;
#pragma unroll
            for (int r = 0; r < 4; r++) af[mt][r] = As[buf][base + r * 40];
        }
        uint32_t bf[8][2];
#pragma unroll
        for (int nt = 0; nt < 8; nt++) {
            const int base = ((wn * 8 + nt) * 2) * 33 + lane;
            bf[nt][0] = Bs[buf][base];
            bf[nt][1] = Bs[buf][base + 33];
        }
#pragma unroll
        for (int mt = 0; mt < 4; mt++) {
#pragma unroll
            for (int nt = 0; nt < 8; nt++) {
                asm volatile(
                    "mma.sync.aligned.m16n8k16.row.col.f32.f16.f16.f32 "
                    "{%0,%1,%2,%3}, {%4,%5,%6,%7}, {%8,%9}, {%0,%1,%2,%3};"
                    : "+f"(acc[mt][nt][0]), "+f"(acc[mt][nt][1]),
                      "+f"(acc[mt][nt][2]), "+f"(acc[mt][nt][3])
                    : "r"(af[mt][0]), "r"(af[mt][1]), "r"(af[mt][2]), "r"(af[mt][3]),
                      "r"(bf[nt][0]), "r"(bf[nt][1]));
            }
        }
    };

    load_gmem(0);
    store_smem(0);
    __syncthreads();

    int buf = 0;
    for (int t_ = 0; t_ < NT; t_++) {
        if (t_ + 1 < NT) load_gmem((t_ + 1) * BK);
        compute(buf);
        if (t_ + 1 < NT) store_smem(buf ^ 1);
        __syncthreads();
        buf ^= 1;
    }

    const int g   = lane >> 2;
    const int tig = lane & 3;
#pragma unroll
    for (int mt = 0; mt < 4; mt++) {
        const int r0 = bm + wm * 64 + mt * 16 + g;
#pragma unroll
        for (int nt = 0; nt < 8; nt++) {
            const int col = bn + wn * 64 + nt * 8 + tig * 2;
            const float b0 = __ldg(bias + col);
            const float b1 = __ldg(bias + col + 1);
            float2 v0 = make_float2(acc[mt][nt][0] + b0, acc[mt][nt][1] + b1);
            float2 v1 = make_float2(acc[mt][nt][2] + b0, acc[mt][nt][3] + b1);
            *(float2*)(C + (size_t)r0 * N + col)       = v0;
            *(float2*)(C + (size_t)(r0 + 8) * N + col) = v1;
        }
    }
}

// ---------------------------------------------------------------------------
// Tensor-core windowed attention: one block per (window, head), 4 warps.
// (unchanged from round 3)
// ---------------------------------------------------------------------------
__global__ __launch_bounds__(128)
void window_attn_tc(const float* __restrict__ qkv,
                    const float* __restrict__ rpb,   // [169, 8]
                    float* __restrict__ out)
{
    __shared__ float sq[64 * 36];
    __shared__ float sk[56 * 36];
    __shared__ float sv[56 * 40];
    __shared__ float sp[64 * 60];
    __shared__ float srpb[169];

    const int b = blockIdx.x;
    const int h = blockIdx.y;
    const int tid  = threadIdx.x;
    const int lane = tid & 31;
    const int warp = tid >> 5;
    const int g = lane >> 2;
    const int t = lane & 3;

    const float scale = 0.17677669529663687f;  // 32^-0.5
    const float* base = qkv + (size_t)b * NTOK * 768 + h * 32;

#pragma unroll
    for (int it = 0; it < 4; it++) {
        const int e = tid + it * 128;
        const int row = e >> 3, c4 = e & 7;
        const int sr = row < NTOK ? row : NTOK - 1;
        float4 v = *(const float4*)(base + (size_t)sr * 768 + c4 * 4);
        uint32_t* d = (uint32_t*)&sq[row * 36 + c4 * 4];
        d[0] = f2tf32(v.x * scale); d[1] = f2tf32(v.y * scale);
        d[2] = f2tf32(v.z * scale); d[3] = f2tf32(v.w * scale);
    }
#pragma unroll
    for (int it = 0; it < 4; it++) {
        const int e = tid + it * 128;
        if (e < 448) {
            const int row = e >> 3, c4 = e & 7;
            const int sr = row < NTOK ? row : NTOK - 1;
            float4 v = *(const float4*)(base + (size_t)sr * 768 + 256 + c4 * 4);
            uint32_t* d = (uint32_t*)&sk[row * 36 + c4 * 4];
            d[0] = f2tf32(v.x); d[1] = f2tf32(v.y);
            d[2] = f2tf32(v.z); d[3] = f2tf32(v.w);
        }
    }
#pragma unroll
    for (int it = 0; it < 4; it++) {
        const int e = tid + it * 128;
        if (e < 448) {
            const int row = e >> 3, c4 = e & 7;
            const int sr = row < NTOK ? row : NTOK - 1;
            float4 v = *(const float4*)(base + (size_t)sr * 768 + 512 + c4 * 4);
            uint32_t* d = (uint32_t*)&sv[row * 40 + c4 * 4];
            d[0] = f2tf32(v.x); d[1] = f2tf32(v.y);
            d[2] = f2tf32(v.z); d[3] = f2tf32(v.w);
        }
    }
    for (int e = tid; e < 169; e += 128) srpb[e] = rpb[e * 8 + h];
    __syncthreads();

    const int mtb = warp * 16;
    float sc[7][4];
#pragma unroll
    for (int nt = 0; nt < 7; nt++)
#pragma unroll
        for (int r = 0; r < 4; r++) sc[nt][r] = 0.f;

#pragma unroll
    for (int ko = 0; ko < 4; ko++) {
        uint32_t a0, a1, a2, a3;
        {
            const float* p0 = &sq[(mtb + g) * 36 + ko * 8 + t];
            const float* p1 = &sq[(mtb + g + 8) * 36 + ko * 8 + t];
            a0 = __float_as_uint(p0[0]); a2 = __float_as_uint(p0[4]);
            a1 = __float_as_uint(p1[0]); a3 = __float_as_uint(p1[4]);
        }
#pragma unroll
        for (int nt = 0; nt < 7; nt++) {
            const float* pb = &sk[(nt * 8 + g) * 36 + ko * 8 + t];
            uint32_t b0 = __float_as_uint(pb[0]);
            uint32_t b1 = __float_as_uint(pb[4]);
            asm volatile(
                "mma.sync.aligned.m16n8k8.row.col.f32.tf32.tf32.f32 "
                "{%0,%1,%2,%3}, {%4,%5,%6,%7}, {%8,%9}, {%0,%1,%2,%3};"
                : "+f"(sc[nt][0]), "+f"(sc[nt][1]), "+f"(sc[nt][2]), "+f"(sc[nt][3])
                : "r"(a0), "r"(a1), "r"(a2), "r"(a3), "r"(b0), "r"(b1));
        }
    }

    const int i0 = mtb + g, i1 = i0 + 8;
    const int xi0 = i0 / 7, yi0 = i0 - xi0 * 7;
    const int xi1 = i1 / 7, yi1 = i1 - xi1 * 7;
    const bool v0 = i0 < NTOK, v1 = i1 < NTOK;

    float m0 = -1e30f, m1 = -1e30f;
#pragma unroll
    for (int nt = 0; nt < 7; nt++) {
#pragma unroll
        for (int e = 0; e < 2; e++) {
            const int j = nt * 8 + 2 * t + e;
            const bool jv = j < NTOK;
            const int xj = j / 7, yj = j - xj * 7;
            if (v0 && jv)
                sc[nt][e] += srpb[(xi0 - xj + 6) * 13 + (yi0 - yj + 6)];
            else
                sc[nt][e] = -1e30f;
            if (v1 && jv)
                sc[nt][2 + e] += srpb[(xi1 - xj + 6) * 13 + (yi1 - yj + 6)];
            else
                sc[nt][2 + e] = -1e30f;
            m0 = fmaxf(m0, sc[nt][e]);
            m1 = fmaxf(m1, sc[nt][2 + e]);
        }
    }
    m0 = fmaxf(m0, __shfl_xor_sync(0xffffffffu, m0, 1));
    m0 = fmaxf(m0, __shfl_xor_sync(0xffffffffu, m0, 2));
    m1 = fmaxf(m1, __shfl_xor_sync(0xffffffffu, m1, 1));
    m1 = fmaxf(m1, __shfl_xor_sync(0xffffffffu, m1, 2));

    float s0 = 0.f, s1 = 0.f;
#pragma unroll
    for (int nt = 0; nt < 7; nt++) {
#pragma unroll
        for (int e = 0; e < 2; e++) {
            float p0 = __expf(sc[nt][e] - m0);
            float p1 = __expf(sc[nt][2 + e] - m1);
            sc[nt][e] = p0;  sc[nt][2 + e] = p1;
            s0 += p0;  s1 += p1;
        }
    }
    s0 += __shfl_xor_sync(0xffffffffu, s0, 1);
    s0 += __shfl_xor_sync(0xffffffffu, s0, 2);
    s1 += __shfl_xor_sync(0xffffffffu, s1, 1);
    s1 += __shfl_xor_sync(0xffffffffu, s1, 2);
    const float inv0 = 1.f / s0, inv1 = 1.f / s1;

#pragma unroll
    for (int nt = 0; nt < 7; nt++) {
        const int j = nt * 8 + 2 * t;
        uint32_t* d0 = (uint32_t*)&sp[i0 * 60 + j];
        uint32_t* d1 = (uint32_t*)&sp[i1 * 60 + j];
        d0[0] = f2tf32(sc[nt][0]); d0[1] = f2tf32(sc[nt][1]);
        d1[0] = f2tf32(sc[nt][2]); d1[1] = f2tf32(sc[nt][3]);
    }
    __syncwarp();

    float ov[4][4];
#pragma unroll
    for (int nt = 0; nt < 4; nt++)
#pragma unroll
        for (int r = 0; r < 4; r++) ov[nt][r] = 0.f;

#pragma unroll
    for (int ko = 0; ko < 7; ko++) {
        uint32_t a0, a1, a2, a3;
        {
            const float* p0 = &sp[(mtb + g) * 60 + ko * 8 + t];
            const float* p1 = &sp[(mtb + g + 8) * 60 + ko * 8 + t];
            a0 = __float_as_uint(p0[0]); a2 = __float_as_uint(p0[4]);
            a1 = __float_as_uint(p1[0]); a3 = __float_as_uint(p1[4]);
        }
#pragma unroll
        for (int nt = 0; nt < 4; nt++) {
            const float* pb = &sv[(ko * 8 + t) * 40 + nt * 8 + g];
            uint32_t b0 = __float_as_uint(pb[0]);
            uint32_t b1 = __float_as_uint(pb[4 * 40]);
            asm volatile(
                "mma.sync.aligned.m16n8k8.row.col.f32.tf32.tf32.f32 "
                "{%0,%1,%2,%3}, {%4,%5,%6,%7}, {%8,%9}, {%0,%1,%2,%3};"
                : "+f"(ov[nt][0]), "+f"(ov[nt][1]), "+f"(ov[nt][2]), "+f"(ov[nt][3])
                : "r"(a0), "r"(a1), "r"(a2), "r"(a3), "r"(b0), "r"(b1));
        }
    }

#pragma unroll
    for (int nt = 0; nt < 4; nt++) {
        const int col = h * 32 + nt * 8 + 2 * t;
        if (v0) {
            float2 w = make_float2(ov[nt][0] * inv0, ov[nt][1] * inv0);
            *(float2*)(out + ((size_t)b * NTOK + i0) * CDIM + col) = w;
        }
        if (v1) {
            float2 w = make_float2(ov[nt][2] * inv1, ov[nt][3] * inv1);
            *(float2*)(out + ((size_t)b * NTOK + i1) * CDIM + col) = w;
        }
    }
}

// ---------------------------------------------------------------------------
// Launch
// ---------------------------------------------------------------------------
extern "C" void kernel_launch(void* const* d_in, const int* in_sizes, int n_in,
                              void* d_out, int out_size)
{
    const float* x      = (const float*)d_in[0];
    const float* qkv_w  = (const float*)d_in[1];
    const float* qkv_b  = (const float*)d_in[2];
    const float* rpb    = (const float*)d_in[3];
    const float* proj_w = (const float*)d_in[4];
    const float* proj_b = (const float*)d_in[5];
    float* out = (float*)d_out;

    float* qkv = nullptr;
    float* att = nullptr;
    cudaGetSymbolAddress((void**)&qkv, g_qkv);
    cudaGetSymbolAddress((void**)&att, g_att);

    // 1) QKV GEMM: [200704,256] @ [256,768] + bias  (fp16 tensor cores)
    {
        dim3 grid(768 / 128, MROWS / 128);
        h16_gemm_bias<<<grid, 128>>>(x, qkv_w, qkv_b, qkv, MROWS, 768, CDIM);
    }
    // 2) Windowed attention (tensor cores, per window-head)
    {
        dim3 grid(BWIN, NHEAD);
        window_attn_tc<<<grid, 128>>>(qkv, rpb, att);
    }
    // 3) Projection GEMM: [200704,256] @ [256,256] + bias  (fp16 tensor cores)
    {
        dim3 grid(CDIM / 128, MROWS / 128);
        h16_gemm_bias<<<grid, 128>>>(att, proj_w, proj_b, out, MROWS, CDIM, CDIM);
    }
}

// round 5
// speedup vs baseline: 3.9180x; 1.1112x over previous
#include <cuda_runtime.h>
#include <cuda_bf16.h>
#include <cuda_fp16.h>
#include <cstdint>

// Problem constants (fixed by setup_inputs)
#define BWIN   4096          // number of windows
#define NTOK   49            // tokens per window (7x7)
#define CDIM   256           // channels
#define NHEAD  8
#define DHEAD  32
#define MROWS  (BWIN * NTOK) // 200704

// ---------------------------------------------------------------------------
// Scratch (device globals; no runtime allocation allowed)
// ---------------------------------------------------------------------------
__device__ float g_qkv[(size_t)MROWS * 768];   // [B*N, 3C]
__device__ float g_att[(size_t)MROWS * CDIM];  // [B*N, C]

__device__ __forceinline__ uint32_t f2tf32(float f) {
    uint32_t u;
    asm("cvt.rna.tf32.f32 %0, %1;" : "=r"(u) : "f"(f));
    return u;
}
__device__ __forceinline__ uint32_t pack_h2(float a, float b) {
    __half2 h = __floats2half2_rn(a, b);
    return *(uint32_t*)&h;
}

// ---------------------------------------------------------------------------
// fp16 tensor-core GEMM with bias: C[M,N] = A[M,K] @ B[K,N] + bias[N]
// BM=128, BN=128, BK=16, 128 threads (4 warps, warp tile 64x64),
// mma.sync.aligned.m16n8k16.row.col.f32.f16.f16.f32.
// Double-buffered smem + PREFETCH DISTANCE 2 register staging:
//   iter t: LDG(tile t+2) -> compute(tile t) -> STS(tile t+1) -> sync
// so global latency is covered by two full compute phases.
// N, K are template constants (768/256 and 256) to kill address IMADs.
// ---------------------------------------------------------------------------
template<int N, int K>
__global__ __launch_bounds__(128, 2)
void h16_gemm_bias(const float* __restrict__ A,
                   const float* __restrict__ B,
                   const float* __restrict__ bias,
                   float* __restrict__ C)
{
    constexpr int BM = 128, BK = 16;
    constexpr int ASZ = 8 * 4 * 40;   // 1280 words per buffer
    constexpr int BSZ = 16 * 2 * 33;  // 1056 words per buffer
    constexpr int NT  = K / BK;
    __shared__ uint32_t As[2][ASZ];
    __shared__ uint32_t Bs[2][BSZ];

    const int tid  = threadIdx.x;
    const int lane = tid & 31;
    const int warp = tid >> 5;
    const int wm   = warp & 1;
    const int wn   = warp >> 1;

    const int bm = blockIdx.y * BM;
    const int bn = blockIdx.x * 128;

    // A global-load / frag-store mapping
    const int a_r   = tid >> 2;            // 0..31 (m within 32-row group)
    const int a_k   = (tid & 3) * 4;       // 0,4,8,12
    const int a_t   = (a_k & 7) >> 1;      // 0 or 2
    const int a_rb  = (a_k >> 3) * 2;      // 0 or 2
    const int a_rh  = (a_r >> 3) & 1;
    const int a_g   = a_r & 7;
    // B global-load / frag-store mapping (k-pairs so half2 packs along K)
    const int b_n0  = (tid & 63) * 2;      // 0..126
    const int b_kb  = (tid >> 6) * 2;      // 0 or 2
    const int b_nt  = b_n0 >> 3;
    const int b_g   = b_n0 & 7;

    const float* Ag = A + (size_t)bm * K;
    const float* Bg = B + bn;

    float acc[4][8][4];
#pragma unroll
    for (int i = 0; i < 4; i++)
#pragma unroll
        for (int j = 0; j < 8; j++)
#pragma unroll
            for (int r = 0; r < 4; r++) acc[i][j][r] = 0.f;

    // two register staging sets (prefetch distance 2)
    float4 va[2][4];
    float2 vb0[2][4], vb1[2][4];

    auto load_gmem = [&](int s, int k0) {
#pragma unroll
        for (int q = 0; q < 4; q++) {
            const int m_ = q * 32 + a_r;
            va[s][q] = *(const float4*)(Ag + (size_t)m_ * K + k0 + a_k);
        }
#pragma unroll
        for (int q = 0; q < 4; q++) {
            const int k_ = q * 4 + b_kb;
            vb0[s][q] = *(const float2*)(Bg + (size_t)(k0 + k_) * N + b_n0);
            vb1[s][q] = *(const float2*)(Bg + (size_t)(k0 + k_ + 1) * N + b_n0);
        }
    };

    auto store_smem = [&](int buf, int s) {
#pragma unroll
        for (int q = 0; q < 4; q++) {
            const int mt = 2 * q + (a_r >> 4);
            const int addr = (mt * 4 + a_rh + a_rb) * 40 + a_g * 4 + a_t;
            uint2 w;
            w.x = pack_h2(va[s][q].x, va[s][q].y);
            w.y = pack_h2(va[s][q].z, va[s][q].w);
            *(uint2*)&As[buf][addr] = w;
        }
#pragma unroll
        for (int q = 0; q < 4; q++) {
            const int k_  = q * 4 + b_kb;
            const int t   = (k_ & 7) >> 1;
            const int reg = k_ >> 3;
            const int base = (b_nt * 2 + reg) * 33 + b_g * 4 + t;
            Bs[buf][base]     = pack_h2(vb0[s][q].x, vb1[s][q].x);
            Bs[buf][base + 4] = pack_h2(vb0[s][q].y, vb1[s][q].y);
        }
    };

    auto compute = [&](int buf) {
        uint32_t af[4][4];
#pragma unroll
        for (int mt = 0; mt < 4; mt++) {
            const int base = ((wm * 4 + mt) * 4) * 40 + lane;
#pragma unroll
            for (int r = 0; r < 4; r++) af[mt][r] = As[buf][base + r * 40];
        }
        uint32_t bf[8][2];
#pragma unroll
        for (int nt = 0; nt < 8; nt++) {
            const int base = ((wn * 8 + nt) * 2) * 33 + lane;
            bf[nt][0] = Bs[buf][base];
            bf[nt][1] = Bs[buf][base + 33];
        }
#pragma unroll
        for (int mt = 0; mt < 4; mt++) {
#pragma unroll
            for (int nt = 0; nt < 8; nt++) {
                asm volatile(
                    "mma.sync.aligned.m16n8k16.row.col.f32.f16.f16.f32 "
                    "{%0,%1,%2,%3}, {%4,%5,%6,%7}, {%8,%9}, {%0,%1,%2,%3};"
                    : "+f"(acc[mt][nt][0]), "+f"(acc[mt][nt][1]),
                      "+f"(acc[mt][nt][2]), "+f"(acc[mt][nt][3])
                    : "r"(af[mt][0]), "r"(af[mt][1]), "r"(af[mt][2]), "r"(af[mt][3]),
                      "r"(bf[nt][0]), "r"(bf[nt][1]));
            }
        }
    };

    // prologue: tiles 0 and 1 in flight, tile 0 committed to smem
    load_gmem(0, 0);
    load_gmem(1, BK);
    store_smem(0, 0);
    __syncthreads();

    int buf = 0;
#pragma unroll 4
    for (int t_ = 0; t_ < NT; t_++) {
        if (t_ + 2 < NT) load_gmem(t_ & 1, (t_ + 2) * BK);
        compute(buf);
        if (t_ + 1 < NT) store_smem(buf ^ 1, (t_ + 1) & 1);
        __syncthreads();
        buf ^= 1;
    }

    const int g   = lane >> 2;
    const int tig = lane & 3;
#pragma unroll
    for (int mt = 0; mt < 4; mt++) {
        const int r0 = bm + wm * 64 + mt * 16 + g;
#pragma unroll
        for (int nt = 0; nt < 8; nt++) {
            const int col = bn + wn * 64 + nt * 8 + tig * 2;
            const float b0 = __ldg(bias + col);
            const float b1 = __ldg(bias + col + 1);
            float2 v0 = make_float2(acc[mt][nt][0] + b0, acc[mt][nt][1] + b1);
            float2 v1 = make_float2(acc[mt][nt][2] + b0, acc[mt][nt][3] + b1);
            *(float2*)(C + (size_t)r0 * N + col)       = v0;
            *(float2*)(C + (size_t)(r0 + 8) * N + col) = v1;
        }
    }
}

// ---------------------------------------------------------------------------
// Tensor-core windowed attention: one block per (window, head), 4 warps.
// (unchanged from round 3/4)
// ---------------------------------------------------------------------------
__global__ __launch_bounds__(128)
void window_attn_tc(const float* __restrict__ qkv,
                    const float* __restrict__ rpb,   // [169, 8]
                    float* __restrict__ out)
{
    __shared__ float sq[64 * 36];
    __shared__ float sk[56 * 36];
    __shared__ float sv[56 * 40];
    __shared__ float sp[64 * 60];
    __shared__ float srpb[169];

    const int b = blockIdx.x;
    const int h = blockIdx.y;
    const int tid  = threadIdx.x;
    const int lane = tid & 31;
    const int warp = tid >> 5;
    const int g = lane >> 2;
    const int t = lane & 3;

    const float scale = 0.17677669529663687f;  // 32^-0.5
    const float* base = qkv + (size_t)b * NTOK * 768 + h * 32;

#pragma unroll
    for (int it = 0; it < 4; it++) {
        const int e = tid + it * 128;
        const int row = e >> 3, c4 = e & 7;
        const int sr = row < NTOK ? row : NTOK - 1;
        float4 v = *(const float4*)(base + (size_t)sr * 768 + c4 * 4);
        uint32_t* d = (uint32_t*)&sq[row * 36 + c4 * 4];
        d[0] = f2tf32(v.x * scale); d[1] = f2tf32(v.y * scale);
        d[2] = f2tf32(v.z * scale); d[3] = f2tf32(v.w * scale);
    }
#pragma unroll
    for (int it = 0; it < 4; it++) {
        const int e = tid + it * 128;
        if (e < 448) {
            const int row = e >> 3, c4 = e & 7;
            const int sr = row < NTOK ? row : NTOK - 1;
            float4 v = *(const float4*)(base + (size_t)sr * 768 + 256 + c4 * 4);
            uint32_t* d = (uint32_t*)&sk[row * 36 + c4 * 4];
            d[0] = f2tf32(v.x); d[1] = f2tf32(v.y);
            d[2] = f2tf32(v.z); d[3] = f2tf32(v.w);
        }
    }
#pragma unroll
    for (int it = 0; it < 4; it++) {
        const int e = tid + it * 128;
        if (e < 448) {
            const int row = e >> 3, c4 = e & 7;
            const int sr = row < NTOK ? row : NTOK - 1;
            float4 v = *(const float4*)(base + (size_t)sr * 768 + 512 + c4 * 4);
            uint32_t* d = (uint32_t*)&sv[row * 40 + c4 * 4];
            d[0] = f2tf32(v.x); d[1] = f2tf32(v.y);
            d[2] = f2tf32(v.z); d[3] = f2tf32(v.w);
        }
    }
    for (int e = tid; e < 169; e += 128) srpb[e] = rpb[e * 8 + h];
    __syncthreads();

    const int mtb = warp * 16;
    float sc[7][4];
#pragma unroll
    for (int nt = 0; nt < 7; nt++)
#pragma unroll
        for (int r = 0; r < 4; r++) sc[nt][r] = 0.f;

#pragma unroll
    for (int ko = 0; ko < 4; ko++) {
        uint32_t a0, a1, a2, a3;
        {
            const float* p0 = &sq[(mtb + g) * 36 + ko * 8 + t];
            const float* p1 = &sq[(mtb + g + 8) * 36 + ko * 8 + t];
            a0 = __float_as_uint(p0[0]); a2 = __float_as_uint(p0[4]);
            a1 = __float_as_uint(p1[0]); a3 = __float_as_uint(p1[4]);
        }
#pragma unroll
        for (int nt = 0; nt < 7; nt++) {
            const float* pb = &sk[(nt * 8 + g) * 36 + ko * 8 + t];
            uint32_t b0 = __float_as_uint(pb[0]);
            uint32_t b1 = __float_as_uint(pb[4]);
            asm volatile(
                "mma.sync.aligned.m16n8k8.row.col.f32.tf32.tf32.f32 "
                "{%0,%1,%2,%3}, {%4,%5,%6,%7}, {%8,%9}, {%0,%1,%2,%3};"
                : "+f"(sc[nt][0]), "+f"(sc[nt][1]), "+f"(sc[nt][2]), "+f"(sc[nt][3])
                : "r"(a0), "r"(a1), "r"(a2), "r"(a3), "r"(b0), "r"(b1));
        }
    }

    const int i0 = mtb + g, i1 = i0 + 8;
    const int xi0 = i0 / 7, yi0 = i0 - xi0 * 7;
    const int xi1 = i1 / 7, yi1 = i1 - xi1 * 7;
    const bool v0 = i0 < NTOK, v1 = i1 < NTOK;

    float m0 = -1e30f, m1 = -1e30f;
#pragma unroll
    for (int nt = 0; nt < 7; nt++) {
#pragma unroll
        for (int e = 0; e < 2; e++) {
            const int j = nt * 8 + 2 * t + e;
            const bool jv = j < NTOK;
            const int xj = j / 7, yj = j - xj * 7;
            if (v0 && jv)
                sc[nt][e] += srpb[(xi0 - xj + 6) * 13 + (yi0 - yj + 6)];
            else
                sc[nt][e] = -1e30f;
            if (v1 && jv)
                sc[nt][2 + e] += srpb[(xi1 - xj + 6) * 13 + (yi1 - yj + 6)];
            else
                sc[nt][2 + e] = -1e30f;
            m0 = fmaxf(m0, sc[nt][e]);
            m1 = fmaxf(m1, sc[nt][2 + e]);
        }
    }
    m0 = fmaxf(m0, __shfl_xor_sync(0xffffffffu, m0, 1));
    m0 = fmaxf(m0, __shfl_xor_sync(0xffffffffu, m0, 2));
    m1 = fmaxf(m1, __shfl_xor_sync(0xffffffffu, m1, 1));
    m1 = fmaxf(m1, __shfl_xor_sync(0xffffffffu, m1, 2));

    float s0 = 0.f, s1 = 0.f;
#pragma unroll
    for (int nt = 0; nt < 7; nt++) {
#pragma unroll
        for (int e = 0; e < 2; e++) {
            float p0 = __expf(sc[nt][e] - m0);
            float p1 = __expf(sc[nt][2 + e] - m1);
            sc[nt][e] = p0;  sc[nt][2 + e] = p1;
            s0 += p0;  s1 += p1;
        }
    }
    s0 += __shfl_xor_sync(0xffffffffu, s0, 1);
    s0 += __shfl_xor_sync(0xffffffffu, s0, 2);
    s1 += __shfl_xor_sync(0xffffffffu, s1, 1);
    s1 += __shfl_xor_sync(0xffffffffu, s1, 2);
    const float inv0 = 1.f / s0, inv1 = 1.f / s1;

#pragma unroll
    for (int nt = 0; nt < 7; nt++) {
        const int j = nt * 8 + 2 * t;
        uint32_t* d0 = (uint32_t*)&sp[i0 * 60 + j];
        uint32_t* d1 = (uint32_t*)&sp[i1 * 60 + j];
        d0[0] = f2tf32(sc[nt][0]); d0[1] = f2tf32(sc[nt][1]);
        d1[0] = f2tf32(sc[nt][2]); d1[1] = f2tf32(sc[nt][3]);
    }
    __syncwarp();

    float ov[4][4];
#pragma unroll
    for (int nt = 0; nt < 4; nt++)
#pragma unroll
        for (int r = 0; r < 4; r++) ov[nt][r] = 0.f;

#pragma unroll
    for (int ko = 0; ko < 7; ko++) {
        uint32_t a0, a1, a2, a3;
        {
            const float* p0 = &sp[(mtb + g) * 60 + ko * 8 + t];
            const float* p1 = &sp[(mtb + g + 8) * 60 + ko * 8 + t];
            a0 = __float_as_uint(p0[0]); a2 = __float_as_uint(p0[4]);
            a1 = __float_as_uint(p1[0]); a3 = __float_as_uint(p1[4]);
        }
#pragma unroll
        for (int nt = 0; nt < 4; nt++) {
            const float* pb = &sv[(ko * 8 + t) * 40 + nt * 8 + g];
            uint32_t b0 = __float_as_uint(pb[0]);
            uint32_t b1 = __float_as_uint(pb[4 * 40]);
            asm volatile(
                "mma.sync.aligned.m16n8k8.row.col.f32.tf32.tf32.f32 "
                "{%0,%1,%2,%3}, {%4,%5,%6,%7}, {%8,%9}, {%0,%1,%2,%3};"
                : "+f"(ov[nt][0]), "+f"(ov[nt][1]), "+f"(ov[nt][2]), "+f"(ov[nt][3])
                : "r"(a0), "r"(a1), "r"(a2), "r"(a3), "r"(b0), "r"(b1));
        }
    }

#pragma unroll
    for (int nt = 0; nt < 4; nt++) {
        const int col = h * 32 + nt * 8 + 2 * t;
        if (v0) {
            float2 w = make_float2(ov[nt][0] * inv0, ov[nt][1] * inv0);
            *(float2*)(out + ((size_t)b * NTOK + i0) * CDIM + col) = w;
        }
        if (v1) {
            float2 w = make_float2(ov[nt][2] * inv1, ov[nt][3] * inv1);
            *(float2*)(out + ((size_t)b * NTOK + i1) * CDIM + col) = w;
        }
    }
}

// ---------------------------------------------------------------------------
// Launch
// ---------------------------------------------------------------------------
extern "C" void kernel_launch(void* const* d_in, const int* in_sizes, int n_in,
                              void* d_out, int out_size)
{
    const float* x      = (const float*)d_in[0];
    const float* qkv_w  = (const float*)d_in[1];
    const float* qkv_b  = (const float*)d_in[2];
    const float* rpb    = (const float*)d_in[3];
    const float* proj_w = (const float*)d_in[4];
    const float* proj_b = (const float*)d_in[5];
    float* out = (float*)d_out;

    float* qkv = nullptr;
    float* att = nullptr;
    cudaGetSymbolAddress((void**)&qkv, g_qkv);
    cudaGetSymbolAddress((void**)&att, g_att);

    // 1) QKV GEMM: [200704,256] @ [256,768] + bias  (fp16 tensor cores)
    {
        dim3 grid(768 / 128, MROWS / 128);
        h16_gemm_bias<768, 256><<<grid, 128>>>(x, qkv_w, qkv_b, qkv);
    }
    // 2) Windowed attention (tensor cores, per window-head)
    {
        dim3 grid(BWIN, NHEAD);
        window_attn_tc<<<grid, 128>>>(qkv, rpb, att);
    }
    // 3) Projection GEMM: [200704,256] @ [256,256] + bias  (fp16 tensor cores)
    {
        dim3 grid(CDIM / 128, MROWS / 128);
        h16_gemm_bias<256, 256><<<grid, 128>>>(att, proj_w, proj_b, out);
    }
}

// round 6
// speedup vs baseline: 4.3968x; 1.1222x over previous
#include <cuda_runtime.h>
#include <cuda_fp16.h>
#include <cstdint>

// Problem constants (fixed by setup_inputs)
#define BWIN   4096
#define NTOK   49
#define CDIM   256
#define NHEAD  8
#define MROWS  (BWIN * NTOK)   // 200704

// ---------------------------------------------------------------------------
// Scratch (device globals; no runtime allocation allowed)
// ---------------------------------------------------------------------------
__device__ __half   g_qkv[(size_t)MROWS * 768];      // fp16 qkv scratch
__device__ __half   g_att[(size_t)MROWS * CDIM];     // fp16 attention output
__device__ uint32_t g_wqkv[6 * 16 * 32 * 32];        // qkv_w, frag-major fp16 words
__device__ uint32_t g_wproj[2 * 16 * 32 * 32];       // proj_w, frag-major fp16 words

__device__ __forceinline__ uint32_t f2tf32(float f) {
    uint32_t u;
    asm("cvt.rna.tf32.f32 %0, %1;" : "=r"(u) : "f"(f));
    return u;
}
__device__ __forceinline__ uint32_t pack_h2(float a, float b) {
    __half2 h = __floats2half2_rn(a, b);
    return *(uint32_t*)&h;
}

// ---------------------------------------------------------------------------
// Weight conversion: fp32 [K,N] row-major -> fp16 fragment-major words.
// Word layout: idx = ((nblk*16 + kc)*32 + (nt*2+reg))*32 + lane,
//   lane = g*4 + t;  n = nblk*128 + nt*8 + g;  k = kc*16 + reg*8 + t*2;
//   word = half2(w[k][n], w[k+1][n]).
// Grid must satisfy grid*256 == NBLK*16*1024.
// ---------------------------------------------------------------------------
__global__ void convert_w(const float* __restrict__ w, uint32_t* __restrict__ dst, int N)
{
    const int idx  = blockIdx.x * 256 + threadIdx.x;
    const int lane = idx & 31;
    const int row  = (idx >> 5) & 31;      // nt*2 + reg
    const int kc   = (idx >> 10) & 15;
    const int nblk = idx >> 14;
    const int nt = row >> 1, reg = row & 1;
    const int g = lane >> 2, t = lane & 3;
    const int n = nblk * 128 + nt * 8 + g;
    const int k = kc * 16 + reg * 8 + t * 2;
    dst[idx] = pack_h2(w[(size_t)k * N + n], w[(size_t)(k + 1) * N + n]);
}

// ---------------------------------------------------------------------------
// A-resident fp16 tensor-core GEMM: C[M,N] = A[M,K] @ B[K,N] + bias.
// One CTA owns 128 rows and loops over all N/128 column blocks.
// A converted to fp16 fragment layout ONCE in smem (64KB), reused throughout.
// B consumed pre-converted frag-major (g_wqkv/g_wproj): trivial coalesced
// LDG.128 -> STS.128 fill, double-buffered, prefetch distance 2.
// TA: float (convert on fill) or __half (direct). TC: __half or float.
// ---------------------------------------------------------------------------
template<typename TA, typename TC, int N, int K>
__global__ __launch_bounds__(128, 2)
void h16_gemm(const TA* __restrict__ A, const uint32_t* __restrict__ Bw,
              const float* __restrict__ bias, TC* __restrict__ C)
{
    constexpr int BK = 16, NT = K / BK, NBLK = N / 128;
    extern __shared__ uint32_t smem[];
    uint32_t* Asm = smem;                 // NT*8*4*32 = 16384 words (64KB)
    uint32_t* Bsm = smem + NT * 8 * 4 * 32;  // 2 buffers x 1024 words

    const int tid  = threadIdx.x;
    const int lane = tid & 31;
    const int warp = tid >> 5;
    const int wm   = warp & 1;
    const int wn   = warp >> 1;
    const int bm   = blockIdx.x * 128;

    const int a_r  = tid >> 2;            // 0..31
    const int a_k  = (tid & 3) * 4;       // 0,4,8,12
    const int a_t  = (a_k & 7) >> 1;      // 0 or 2
    const int a_rb = (a_k >> 3) * 2;      // 0 or 2

    // ---- A resident fill (once) -------------------------------------------
    const TA* Ag = A + (size_t)bm * K;
#pragma unroll
    for (int kc = 0; kc < NT; kc++) {
#pragma unroll
        for (int q = 0; q < 4; q++) {
            const int row = q * 32 + a_r;
            const int mt = row >> 4, rh = (row >> 3) & 1, g = row & 7;
            uint2 w;
            if constexpr (sizeof(TA) == 4) {
                float4 v = *(const float4*)(Ag + (size_t)row * K + kc * 16 + a_k);
                w.x = pack_h2(v.x, v.y);
                w.y = pack_h2(v.z, v.w);
            } else {
                w = *(const uint2*)(Ag + (size_t)row * K + kc * 16 + a_k);
            }
            *(uint2*)&Asm[((kc * 8 + mt) * 4 + rh + a_rb) * 32 + g * 4 + a_t] = w;
        }
    }

    uint4 stage[2][2];
    auto loadB = [&](int s, int kc, const uint32_t* bw) {
        const uint4* p = (const uint4*)(bw + kc * 1024) + tid * 2;
        stage[s][0] = p[0];
        stage[s][1] = p[1];
    };
    auto stsB = [&](int buf, int s) {
        uint4* d = (uint4*)(Bsm + buf * 1024) + tid * 2;
        d[0] = stage[s][0];
        d[1] = stage[s][1];
    };

    float acc[4][8][4];

    auto compute = [&](int buf, int kc) {
        uint32_t af[4][4];
#pragma unroll
        for (int mt = 0; mt < 4; mt++) {
            const int base = ((kc * 8 + wm * 4 + mt) * 4) * 32 + lane;
#pragma unroll
            for (int r = 0; r < 4; r++) af[mt][r] = Asm[base + r * 32];
        }
        uint32_t bf[8][2];
        const uint32_t* bp = Bsm + buf * 1024;
#pragma unroll
        for (int nt = 0; nt < 8; nt++) {
            bf[nt][0] = bp[((wn * 8 + nt) * 2 + 0) * 32 + lane];
            bf[nt][1] = bp[((wn * 8 + nt) * 2 + 1) * 32 + lane];
        }
#pragma unroll
        for (int mt = 0; mt < 4; mt++) {
#pragma unroll
            for (int nt = 0; nt < 8; nt++) {
                asm volatile(
                    "mma.sync.aligned.m16n8k16.row.col.f32.f16.f16.f32 "
                    "{%0,%1,%2,%3}, {%4,%5,%6,%7}, {%8,%9}, {%0,%1,%2,%3};"
                    : "+f"(acc[mt][nt][0]), "+f"(acc[mt][nt][1]),
                      "+f"(acc[mt][nt][2]), "+f"(acc[mt][nt][3])
                    : "r"(af[mt][0]), "r"(af[mt][1]), "r"(af[mt][2]), "r"(af[mt][3]),
                      "r"(bf[nt][0]), "r"(bf[nt][1]));
            }
        }
    };

    // ---- N-block loop -------------------------------------------------------
    for (int nblk = 0; nblk < NBLK; nblk++) {
        const uint32_t* bw = Bw + (size_t)nblk * NT * 1024;
#pragma unroll
        for (int i = 0; i < 4; i++)
#pragma unroll
            for (int j = 0; j < 8; j++)
#pragma unroll
                for (int r = 0; r < 4; r++) acc[i][j][r] = 0.f;

        loadB(0, 0, bw);
        loadB(1, 1, bw);
        stsB(0, 0);
        __syncthreads();

        int buf = 0;
#pragma unroll 2
        for (int t = 0; t < NT; t++) {
            if (t + 2 < NT) loadB(t & 1, t + 2, bw);
            compute(buf, t);
            if (t + 1 < NT) stsB(buf ^ 1, (t + 1) & 1);
            __syncthreads();
            buf ^= 1;
        }

        // epilogue: bias + store
        const int g = lane >> 2, tig = lane & 3;
#pragma unroll
        for (int mt = 0; mt < 4; mt++) {
            const int r0 = bm + wm * 64 + mt * 16 + g;
#pragma unroll
            for (int nt = 0; nt < 8; nt++) {
                const int col = nblk * 128 + wn * 64 + nt * 8 + tig * 2;
                const float b0 = __ldg(bias + col);
                const float b1 = __ldg(bias + col + 1);
                if constexpr (sizeof(TC) == 2) {
                    __half* cp = (__half*)C;
                    *(__half2*)(cp + (size_t)r0 * N + col) =
                        __floats2half2_rn(acc[mt][nt][0] + b0, acc[mt][nt][1] + b1);
                    *(__half2*)(cp + (size_t)(r0 + 8) * N + col) =
                        __floats2half2_rn(acc[mt][nt][2] + b0, acc[mt][nt][3] + b1);
                } else {
                    float* cp = (float*)C;
                    *(float2*)(cp + (size_t)r0 * N + col) =
                        make_float2(acc[mt][nt][0] + b0, acc[mt][nt][1] + b1);
                    *(float2*)(cp + (size_t)(r0 + 8) * N + col) =
                        make_float2(acc[mt][nt][2] + b0, acc[mt][nt][3] + b1);
                }
            }
        }
    }
}

// ---------------------------------------------------------------------------
// Tensor-core windowed attention (tf32 mma), fp16 in / fp16 out.
// One block per (window, head), 4 warps. exp() skipped on padded rows/cols.
// ---------------------------------------------------------------------------
__global__ __launch_bounds__(128)
void window_attn_tc(const __half* __restrict__ qkv,
                    const float* __restrict__ rpb,   // [169, 8]
                    __half* __restrict__ out)
{
    __shared__ float sq[64 * 36];
    __shared__ float sk[56 * 36];
    __shared__ float sv[56 * 40];
    __shared__ float sp[64 * 60];
    __shared__ float srpb[169];

    const int b = blockIdx.x;
    const int h = blockIdx.y;
    const int tid  = threadIdx.x;
    const int lane = tid & 31;
    const int warp = tid >> 5;
    const int g = lane >> 2;
    const int t = lane & 3;

    const float scale = 0.17677669529663687f;  // 32^-0.5
    const __half* base = qkv + (size_t)b * NTOK * 768 + h * 32;

    // q: 64 rows x 4 uint4 (8 halves each), scaled
#pragma unroll
    for (int it = 0; it < 2; it++) {
        const int e = tid + it * 128;            // 0..255
        const int row = e >> 2, c = e & 3;
        const int sr = row < NTOK ? row : NTOK - 1;
        uint4 raw = *(const uint4*)(base + (size_t)sr * 768 + c * 8);
        const __half2* hp = (const __half2*)&raw;
        uint32_t* d = (uint32_t*)&sq[row * 36 + c * 8];
#pragma unroll
        for (int i = 0; i < 4; i++) {
            float2 f = __half22float2(hp[i]);
            d[2 * i]     = f2tf32(f.x * scale);
            d[2 * i + 1] = f2tf32(f.y * scale);
        }
    }
    // k: 56 rows
#pragma unroll
    for (int it = 0; it < 2; it++) {
        const int e = tid + it * 128;
        if (e < 224) {
            const int row = e >> 2, c = e & 3;
            const int sr = row < NTOK ? row : NTOK - 1;
            uint4 raw = *(const uint4*)(base + (size_t)sr * 768 + 256 + c * 8);
            const __half2* hp = (const __half2*)&raw;
            uint32_t* d = (uint32_t*)&sk[row * 36 + c * 8];
#pragma unroll
            for (int i = 0; i < 4; i++) {
                float2 f = __half22float2(hp[i]);
                d[2 * i]     = f2tf32(f.x);
                d[2 * i + 1] = f2tf32(f.y);
            }
        }
    }
    // v: 56 rows
#pragma unroll
    for (int it = 0; it < 2; it++) {
        const int e = tid + it * 128;
        if (e < 224) {
            const int row = e >> 2, c = e & 3;
            const int sr = row < NTOK ? row : NTOK - 1;
            uint4 raw = *(const uint4*)(base + (size_t)sr * 768 + 512 + c * 8);
            const __half2* hp = (const __half2*)&raw;
            uint32_t* d = (uint32_t*)&sv[row * 40 + c * 8];
#pragma unroll
            for (int i = 0; i < 4; i++) {
                float2 f = __half22float2(hp[i]);
                d[2 * i]     = f2tf32(f.x);
                d[2 * i + 1] = f2tf32(f.y);
            }
        }
    }
    for (int e = tid; e < 169; e += 128) srpb[e] = rpb[e * 8 + h];
    __syncthreads();

    // ---- QK^T ---------------------------------------------------------------
    const int mtb = warp * 16;
    float sc[7][4];
#pragma unroll
    for (int nt = 0; nt < 7; nt++)
#pragma unroll
        for (int r = 0; r < 4; r++) sc[nt][r] = 0.f;

#pragma unroll
    for (int ko = 0; ko < 4; ko++) {
        uint32_t a0, a1, a2, a3;
        {
            const float* p0 = &sq[(mtb + g) * 36 + ko * 8 + t];
            const float* p1 = &sq[(mtb + g + 8) * 36 + ko * 8 + t];
            a0 = __float_as_uint(p0[0]); a2 = __float_as_uint(p0[4]);
            a1 = __float_as_uint(p1[0]); a3 = __float_as_uint(p1[4]);
        }
#pragma unroll
        for (int nt = 0; nt < 7; nt++) {
            const float* pb = &sk[(nt * 8 + g) * 36 + ko * 8 + t];
            uint32_t b0 = __float_as_uint(pb[0]);
            uint32_t b1 = __float_as_uint(pb[4]);
            asm volatile(
                "mma.sync.aligned.m16n8k8.row.col.f32.tf32.tf32.f32 "
                "{%0,%1,%2,%3}, {%4,%5,%6,%7}, {%8,%9}, {%0,%1,%2,%3};"
                : "+f"(sc[nt][0]), "+f"(sc[nt][1]), "+f"(sc[nt][2]), "+f"(sc[nt][3])
                : "r"(a0), "r"(a1), "r"(a2), "r"(a3), "r"(b0), "r"(b1));
        }
    }

    // ---- bias + mask + softmax (exp only on valid entries) -------------------
    const int i0 = mtb + g, i1 = i0 + 8;
    const int xi0 = i0 / 7, yi0 = i0 - xi0 * 7;
    const int xi1 = i1 / 7, yi1 = i1 - xi1 * 7;
    const bool v0 = i0 < NTOK, v1 = i1 < NTOK;

    float m0 = -1e30f, m1 = -1e30f;
#pragma unroll
    for (int nt = 0; nt < 7; nt++) {
#pragma unroll
        for (int e = 0; e < 2; e++) {
            const int j = nt * 8 + 2 * t + e;
            const bool jv = j < NTOK;
            const int xj = j / 7, yj = j - xj * 7;
            if (v0 && jv)
                sc[nt][e] += srpb[(xi0 - xj + 6) * 13 + (yi0 - yj + 6)];
            else
                sc[nt][e] = -1e30f;
            if (v1 && jv)
                sc[nt][2 + e] += srpb[(xi1 - xj + 6) * 13 + (yi1 - yj + 6)];
            else
                sc[nt][2 + e] = -1e30f;
            m0 = fmaxf(m0, sc[nt][e]);
            m1 = fmaxf(m1, sc[nt][2 + e]);
        }
    }
    m0 = fmaxf(m0, __shfl_xor_sync(0xffffffffu, m0, 1));
    m0 = fmaxf(m0, __shfl_xor_sync(0xffffffffu, m0, 2));
    m1 = fmaxf(m1, __shfl_xor_sync(0xffffffffu, m1, 1));
    m1 = fmaxf(m1, __shfl_xor_sync(0xffffffffu, m1, 2));

    float s0 = 0.f, s1 = 0.f;
#pragma unroll
    for (int nt = 0; nt < 7; nt++) {
#pragma unroll
        for (int e = 0; e < 2; e++) {
            const int j = nt * 8 + 2 * t + e;
            const bool jv = j < NTOK;
            if (v0 && jv) {
                float p = __expf(sc[nt][e] - m0);
                sc[nt][e] = p;  s0 += p;
            } else sc[nt][e] = 0.f;
            if (v1 && jv) {
                float p = __expf(sc[nt][2 + e] - m1);
                sc[nt][2 + e] = p;  s1 += p;
            } else sc[nt][2 + e] = 0.f;
        }
    }
    s0 += __shfl_xor_sync(0xffffffffu, s0, 1);
    s0 += __shfl_xor_sync(0xffffffffu, s0, 2);
    s1 += __shfl_xor_sync(0xffffffffu, s1, 1);
    s1 += __shfl_xor_sync(0xffffffffu, s1, 2);
    const float inv0 = v0 ? 1.f / s0 : 0.f;
    const float inv1 = v1 ? 1.f / s1 : 0.f;

    // write exp(S) (unnormalized, tf32) for AV fragments
#pragma unroll
    for (int nt = 0; nt < 7; nt++) {
        const int j = nt * 8 + 2 * t;
        uint32_t* d0 = (uint32_t*)&sp[i0 * 60 + j];
        uint32_t* d1 = (uint32_t*)&sp[i1 * 60 + j];
        d0[0] = f2tf32(sc[nt][0]); d0[1] = f2tf32(sc[nt][1]);
        d1[0] = f2tf32(sc[nt][2]); d1[1] = f2tf32(sc[nt][3]);
    }
    __syncwarp();

    // ---- AV ------------------------------------------------------------------
    float ov[4][4];
#pragma unroll
    for (int nt = 0; nt < 4; nt++)
#pragma unroll
        for (int r = 0; r < 4; r++) ov[nt][r] = 0.f;

#pragma unroll
    for (int ko = 0; ko < 7; ko++) {
        uint32_t a0, a1, a2, a3;
        {
            const float* p0 = &sp[(mtb + g) * 60 + ko * 8 + t];
            const float* p1 = &sp[(mtb + g + 8) * 60 + ko * 8 + t];
            a0 = __float_as_uint(p0[0]); a2 = __float_as_uint(p0[4]);
            a1 = __float_as_uint(p1[0]); a3 = __float_as_uint(p1[4]);
        }
#pragma unroll
        for (int nt = 0; nt < 4; nt++) {
            const float* pb = &sv[(ko * 8 + t) * 40 + nt * 8 + g];
            uint32_t b0 = __float_as_uint(pb[0]);
            uint32_t b1 = __float_as_uint(pb[4 * 40]);
            asm volatile(
                "mma.sync.aligned.m16n8k8.row.col.f32.tf32.tf32.f32 "
                "{%0,%1,%2,%3}, {%4,%5,%6,%7}, {%8,%9}, {%0,%1,%2,%3};"
                : "+f"(ov[nt][0]), "+f"(ov[nt][1]), "+f"(ov[nt][2]), "+f"(ov[nt][3])
                : "r"(a0), "r"(a1), "r"(a2), "r"(a3), "r"(b0), "r"(b1));
        }
    }

    // ---- output (fp16) --------------------------------------------------------
#pragma unroll
    for (int nt = 0; nt < 4; nt++) {
        const int col = h * 32 + nt * 8 + 2 * t;
        if (v0) {
            *(__half2*)(out + ((size_t)b * NTOK + i0) * CDIM + col) =
                __floats2half2_rn(ov[nt][0] * inv0, ov[nt][1] * inv0);
        }
        if (v1) {
            *(__half2*)(out + ((size_t)b * NTOK + i1) * CDIM + col) =
                __floats2half2_rn(ov[nt][2] * inv1, ov[nt][3] * inv1);
        }
    }
}

// ---------------------------------------------------------------------------
// Launch
// ---------------------------------------------------------------------------
extern "C" void kernel_launch(void* const* d_in, const int* in_sizes, int n_in,
                              void* d_out, int out_size)
{
    const float* x      = (const float*)d_in[0];
    const float* qkv_w  = (const float*)d_in[1];
    const float* qkv_b  = (const float*)d_in[2];
    const float* rpb    = (const float*)d_in[3];
    const float* proj_w = (const float*)d_in[4];
    const float* proj_b = (const float*)d_in[5];
    float* out = (float*)d_out;

    __half* qkvh = nullptr;
    __half* atth = nullptr;
    uint32_t* wqkv = nullptr;
    uint32_t* wproj = nullptr;
    cudaGetSymbolAddress((void**)&qkvh, g_qkv);
    cudaGetSymbolAddress((void**)&atth, g_att);
    cudaGetSymbolAddress((void**)&wqkv, g_wqkv);
    cudaGetSymbolAddress((void**)&wproj, g_wproj);

    constexpr int SMEM = (16 * 8 * 4 * 32 + 2 * 1024) * 4;  // 73728 B
    cudaFuncSetAttribute(h16_gemm<float, __half, 768, 256>,
                         cudaFuncAttributeMaxDynamicSharedMemorySize, SMEM);
    cudaFuncSetAttribute(h16_gemm<__half, float, 256, 256>,
                         cudaFuncAttributeMaxDynamicSharedMemorySize, SMEM);

    // 0) weight conversion to frag-major fp16 (tiny)
    convert_w<<<384, 256>>>(qkv_w, wqkv, 768);
    convert_w<<<128, 256>>>(proj_w, wproj, 256);

    // 1) QKV GEMM (A-resident, fp16 out)
    h16_gemm<float, __half, 768, 256><<<MROWS / 128, 128, SMEM>>>(x, wqkv, qkv_b, qkvh);

    // 2) Windowed attention
    {
        dim3 grid(BWIN, NHEAD);
        window_attn_tc<<<grid, 128>>>(qkvh, rpb, atth);
    }

    // 3) Projection GEMM (fp16 A, fp32 out)
    h16_gemm<__half, float, 256, 256><<<MROWS / 128, 128, SMEM>>>(atth, wproj, proj_b, out);
}

// round 7
// speedup vs baseline: 4.8175x; 1.0957x over previous
#include <cuda_runtime.h>
#include <cuda_fp16.h>
#include <cstdint>

// Problem constants (fixed by setup_inputs)
#define BWIN   4096
#define NTOK   49
#define CDIM   256
#define NHEAD  8
#define MROWS  (BWIN * NTOK)   // 200704

// ---------------------------------------------------------------------------
// Scratch (device globals; no runtime allocation allowed)
// ---------------------------------------------------------------------------
__device__ __half   g_qkv[(size_t)MROWS * 768];      // fp16 qkv scratch
__device__ __half   g_att[(size_t)MROWS * CDIM];     // fp16 attention output
__device__ uint32_t g_wqkv[6 * 16 * 32 * 32];        // qkv_w, frag-major fp16 words
__device__ uint32_t g_wproj[2 * 16 * 32 * 32];       // proj_w, frag-major fp16 words

__device__ __forceinline__ uint32_t pack_h2(float a, float b) {
    __half2 h = __floats2half2_rn(a, b);
    return *(uint32_t*)&h;
}

// ---------------------------------------------------------------------------
// Weight conversion: fp32 [K,N] row-major -> fp16 fragment-major words.
//   idx = ((nblk*16 + kc)*32 + (nt*2+reg))*32 + lane, lane = g*4+t
//   n = nblk*128 + nt*8 + g;  k = kc*16 + reg*8 + t*2
//   word = half2(w[k][n], w[k+1][n])
// ---------------------------------------------------------------------------
__global__ void convert_w(const float* __restrict__ w, uint32_t* __restrict__ dst, int N)
{
    const int idx  = blockIdx.x * 256 + threadIdx.x;
    const int lane = idx & 31;
    const int row  = (idx >> 5) & 31;
    const int kc   = (idx >> 10) & 15;
    const int nblk = idx >> 14;
    const int nt = row >> 1, reg = row & 1;
    const int g = lane >> 2, t = lane & 3;
    const int n = nblk * 128 + nt * 8 + g;
    const int k = kc * 16 + reg * 8 + t * 2;
    dst[idx] = pack_h2(w[(size_t)k * N + n], w[(size_t)(k + 1) * N + n]);
}

// ---------------------------------------------------------------------------
// A-resident fp16 tensor-core GEMM (unchanged from round 6)
// ---------------------------------------------------------------------------
template<typename TA, typename TC, int N, int K>
__global__ __launch_bounds__(128, 2)
void h16_gemm(const TA* __restrict__ A, const uint32_t* __restrict__ Bw,
              const float* __restrict__ bias, TC* __restrict__ C)
{
    constexpr int BK = 16, NT = K / BK, NBLK = N / 128;
    extern __shared__ uint32_t smem[];
    uint32_t* Asm = smem;
    uint32_t* Bsm = smem + NT * 8 * 4 * 32;

    const int tid  = threadIdx.x;
    const int lane = tid & 31;
    const int warp = tid >> 5;
    const int wm   = warp & 1;
    const int wn   = warp >> 1;
    const int bm   = blockIdx.x * 128;

    const int a_r  = tid >> 2;
    const int a_k  = (tid & 3) * 4;
    const int a_t  = (a_k & 7) >> 1;
    const int a_rb = (a_k >> 3) * 2;

    const TA* Ag = A + (size_t)bm * K;
#pragma unroll
    for (int kc = 0; kc < NT; kc++) {
#pragma unroll
        for (int q = 0; q < 4; q++) {
            const int row = q * 32 + a_r;
            const int mt = row >> 4, rh = (row >> 3) & 1, g = row & 7;
            uint2 w;
            if constexpr (sizeof(TA) == 4) {
                float4 v = *(const float4*)(Ag + (size_t)row * K + kc * 16 + a_k);
                w.x = pack_h2(v.x, v.y);
                w.y = pack_h2(v.z, v.w);
            } else {
                w = *(const uint2*)(Ag + (size_t)row * K + kc * 16 + a_k);
            }
            *(uint2*)&Asm[((kc * 8 + mt) * 4 + rh + a_rb) * 32 + g * 4 + a_t] = w;
        }
    }

    uint4 stage[2][2];
    auto loadB = [&](int s, int kc, const uint32_t* bw) {
        const uint4* p = (const uint4*)(bw + kc * 1024) + tid * 2;
        stage[s][0] = p[0];
        stage[s][1] = p[1];
    };
    auto stsB = [&](int buf, int s) {
        uint4* d = (uint4*)(Bsm + buf * 1024) + tid * 2;
        d[0] = stage[s][0];
        d[1] = stage[s][1];
    };

    float acc[4][8][4];

    auto compute = [&](int buf, int kc) {
        uint32_t af[4][4];
#pragma unroll
        for (int mt = 0; mt < 4; mt++) {
            const int base = ((kc * 8 + wm * 4 + mt) * 4) * 32 + lane;
#pragma unroll
            for (int r = 0; r < 4; r++) af[mt][r] = Asm[base + r * 32];
        }
        uint32_t bf[8][2];
        const uint32_t* bp = Bsm + buf * 1024;
#pragma unroll
        for (int nt = 0; nt < 8; nt++) {
            bf[nt][0] = bp[((wn * 8 + nt) * 2 + 0) * 32 + lane];
            bf[nt][1] = bp[((wn * 8 + nt) * 2 + 1) * 32 + lane];
        }
#pragma unroll
        for (int mt = 0; mt < 4; mt++) {
#pragma unroll
            for (int nt = 0; nt < 8; nt++) {
                asm volatile(
                    "mma.sync.aligned.m16n8k16.row.col.f32.f16.f16.f32 "
                    "{%0,%1,%2,%3}, {%4,%5,%6,%7}, {%8,%9}, {%0,%1,%2,%3};"
                    : "+f"(acc[mt][nt][0]), "+f"(acc[mt][nt][1]),
                      "+f"(acc[mt][nt][2]), "+f"(acc[mt][nt][3])
                    : "r"(af[mt][0]), "r"(af[mt][1]), "r"(af[mt][2]), "r"(af[mt][3]),
                      "r"(bf[nt][0]), "r"(bf[nt][1]));
            }
        }
    };

    for (int nblk = 0; nblk < NBLK; nblk++) {
        const uint32_t* bw = Bw + (size_t)nblk * NT * 1024;
#pragma unroll
        for (int i = 0; i < 4; i++)
#pragma unroll
            for (int j = 0; j < 8; j++)
#pragma unroll
                for (int r = 0; r < 4; r++) acc[i][j][r] = 0.f;

        loadB(0, 0, bw);
        loadB(1, 1, bw);
        stsB(0, 0);
        __syncthreads();

        int buf = 0;
#pragma unroll 2
        for (int t = 0; t < NT; t++) {
            if (t + 2 < NT) loadB(t & 1, t + 2, bw);
            compute(buf, t);
            if (t + 1 < NT) stsB(buf ^ 1, (t + 1) & 1);
            __syncthreads();
            buf ^= 1;
        }

        const int g = lane >> 2, tig = lane & 3;
#pragma unroll
        for (int mt = 0; mt < 4; mt++) {
            const int r0 = bm + wm * 64 + mt * 16 + g;
#pragma unroll
            for (int nt = 0; nt < 8; nt++) {
                const int col = nblk * 128 + wn * 64 + nt * 8 + tig * 2;
                const float b0 = __ldg(bias + col);
                const float b1 = __ldg(bias + col + 1);
                if constexpr (sizeof(TC) == 2) {
                    __half* cp = (__half*)C;
                    *(__half2*)(cp + (size_t)r0 * N + col) =
                        __floats2half2_rn(acc[mt][nt][0] + b0, acc[mt][nt][1] + b1);
                    *(__half2*)(cp + (size_t)(r0 + 8) * N + col) =
                        __floats2half2_rn(acc[mt][nt][2] + b0, acc[mt][nt][3] + b1);
                } else {
                    float* cp = (float*)C;
                    *(float2*)(cp + (size_t)r0 * N + col) =
                        make_float2(acc[mt][nt][0] + b0, acc[mt][nt][1] + b1);
                    *(float2*)(cp + (size_t)(r0 + 8) * N + col) =
                        make_float2(acc[mt][nt][2] + b0, acc[mt][nt][3] + b1);
                }
            }
        }
    }
}

// ---------------------------------------------------------------------------
// PURE fp16 tensor-core windowed attention: one block per (window, head).
// Q/K copied raw (no conversion), V transposed once to [d][token-pair],
// QK^T + AV via m16n8k16 fp16 mma (fp32 accum). Scale folded into softmax.
// All smem strides 36 words: fragment LDS banks = 4g+t, conflict-free.
// ---------------------------------------------------------------------------
__global__ __launch_bounds__(128)
void window_attn_h16(const __half* __restrict__ qkv,
                     const float* __restrict__ rpb,   // [169, 8]
                     __half* __restrict__ out)
{
    __shared__ uint32_t sq [64 * 36];   // Q rows (half2 words along d)
    __shared__ uint32_t sk [56 * 36];   // K rows
    __shared__ uint32_t svT[32 * 36];   // V transposed: [d][token-pair]
    __shared__ uint32_t sp [64 * 36];   // P = exp(S) fp16, rows x token-pairs
    __shared__ float srpb[169];

    const int b = blockIdx.x;
    const int h = blockIdx.y;
    const int tid  = threadIdx.x;
    const int lane = tid & 31;
    const int warp = tid >> 5;
    const int g = lane >> 2;
    const int t = lane & 3;

    const float scale = 0.17677669529663687f;  // 32^-0.5
    const __half* base = qkv + (size_t)b * NTOK * 768 + h * 32;

    // ---- raw copies -----------------------------------------------------
#pragma unroll
    for (int it = 0; it < 2; it++) {           // Q: 64 rows x 4 uint4
        const int e = tid + it * 128;
        const int row = e >> 2, c = e & 3;
        const int sr = row < NTOK ? row : NTOK - 1;
        *(uint4*)&sq[row * 36 + c * 4] =
            *(const uint4*)(base + (size_t)sr * 768 + c * 8);
    }
#pragma unroll
    for (int it = 0; it < 2; it++) {           // K: 56 rows x 4 uint4
        const int e = tid + it * 128;
        if (e < 224) {
            const int row = e >> 2, c = e & 3;
            const int sr = row < NTOK ? row : NTOK - 1;
            *(uint4*)&sk[row * 36 + c * 4] =
                *(const uint4*)(base + (size_t)sr * 768 + 256 + c * 8);
        }
    }
    // V transpose: svT[d][tp] = half2(V[2tp][d], V[2tp+1][d])
    if (tid < 112) {
        const int tp = tid >> 2, dg = tid & 3;
        int t0 = 2 * tp, t1 = 2 * tp + 1;
        if (t0 > NTOK - 1) t0 = NTOK - 1;
        if (t1 > NTOK - 1) t1 = NTOK - 1;
        uint4 r0 = *(const uint4*)(base + (size_t)t0 * 768 + 512 + dg * 8);
        uint4 r1 = *(const uint4*)(base + (size_t)t1 * 768 + 512 + dg * 8);
        const __half* h0 = (const __half*)&r0;
        const __half* h1 = (const __half*)&r1;
#pragma unroll
        for (int i = 0; i < 8; i++) {
            __half2 w = __halves2half2(h0[i], h1[i]);
            svT[(dg * 8 + i) * 36 + tp] = *(uint32_t*)&w;
        }
    }
    // zero padding words (read by ko=3 of AV): sp[:,28..31], svT[:,28..31]
#pragma unroll
    for (int it = 0; it < 2; it++) {
        const int e = tid + it * 128;
        sp[(e >> 2) * 36 + 28 + (e & 3)] = 0;
    }
    svT[(tid >> 2) * 36 + 28 + (tid & 3)] = 0;
    for (int e = tid; e < 169; e += 128) srpb[e] = rpb[e * 8 + h];
    __syncthreads();

    // ---- QK^T: warp computes S[16 x 56] (fp16 mma, K=32 -> 2 ko) ---------
    const int mtb = warp * 16;
    float sc[7][4];
#pragma unroll
    for (int nt = 0; nt < 7; nt++)
#pragma unroll
        for (int r = 0; r < 4; r++) sc[nt][r] = 0.f;

#pragma unroll
    for (int ko = 0; ko < 2; ko++) {
        const uint32_t a0 = sq[(mtb + g) * 36 + ko * 8 + t];
        const uint32_t a1 = sq[(mtb + g + 8) * 36 + ko * 8 + t];
        const uint32_t a2 = sq[(mtb + g) * 36 + ko * 8 + 4 + t];
        const uint32_t a3 = sq[(mtb + g + 8) * 36 + ko * 8 + 4 + t];
#pragma unroll
        for (int nt = 0; nt < 7; nt++) {
            const uint32_t b0 = sk[(nt * 8 + g) * 36 + ko * 8 + t];
            const uint32_t b1 = sk[(nt * 8 + g) * 36 + ko * 8 + 4 + t];
            asm volatile(
                "mma.sync.aligned.m16n8k16.row.col.f32.f16.f16.f32 "
                "{%0,%1,%2,%3}, {%4,%5,%6,%7}, {%8,%9}, {%0,%1,%2,%3};"
                : "+f"(sc[nt][0]), "+f"(sc[nt][1]), "+f"(sc[nt][2]), "+f"(sc[nt][3])
                : "r"(a0), "r"(a1), "r"(a2), "r"(a3), "r"(b0), "r"(b1));
        }
    }

    // ---- scale + bias + mask + softmax ------------------------------------
    const int i0 = mtb + g, i1 = i0 + 8;
    const int xi0 = i0 / 7, yi0 = i0 - xi0 * 7;
    const int xi1 = i1 / 7, yi1 = i1 - xi1 * 7;
    const bool v0 = i0 < NTOK, v1 = i1 < NTOK;

    float m0 = -1e30f, m1 = -1e30f;
#pragma unroll
    for (int nt = 0; nt < 7; nt++) {
#pragma unroll
        for (int e = 0; e < 2; e++) {
            const int j = nt * 8 + 2 * t + e;
            const bool jv = j < NTOK;
            const int xj = j / 7, yj = j - xj * 7;
            if (v0 && jv)
                sc[nt][e] = fmaf(sc[nt][e], scale,
                                 srpb[(xi0 - xj + 6) * 13 + (yi0 - yj + 6)]);
            else
                sc[nt][e] = -1e30f;
            if (v1 && jv)
                sc[nt][2 + e] = fmaf(sc[nt][2 + e], scale,
                                     srpb[(xi1 - xj + 6) * 13 + (yi1 - yj + 6)]);
            else
                sc[nt][2 + e] = -1e30f;
            m0 = fmaxf(m0, sc[nt][e]);
            m1 = fmaxf(m1, sc[nt][2 + e]);
        }
    }
    m0 = fmaxf(m0, __shfl_xor_sync(0xffffffffu, m0, 1));
    m0 = fmaxf(m0, __shfl_xor_sync(0xffffffffu, m0, 2));
    m1 = fmaxf(m1, __shfl_xor_sync(0xffffffffu, m1, 1));
    m1 = fmaxf(m1, __shfl_xor_sync(0xffffffffu, m1, 2));

    float s0 = 0.f, s1 = 0.f;
#pragma unroll
    for (int nt = 0; nt < 7; nt++) {
#pragma unroll
        for (int e = 0; e < 2; e++) {
            const int j = nt * 8 + 2 * t + e;
            const bool jv = j < NTOK;
            if (v0 && jv) {
                float p = __expf(sc[nt][e] - m0);
                sc[nt][e] = p;  s0 += p;
            } else sc[nt][e] = 0.f;
            if (v1 && jv) {
                float p = __expf(sc[nt][2 + e] - m1);
                sc[nt][2 + e] = p;  s1 += p;
            } else sc[nt][2 + e] = 0.f;
        }
    }
    s0 += __shfl_xor_sync(0xffffffffu, s0, 1);
    s0 += __shfl_xor_sync(0xffffffffu, s0, 2);
    s1 += __shfl_xor_sync(0xffffffffu, s1, 1);
    s1 += __shfl_xor_sync(0xffffffffu, s1, 2);
    const float inv0 = v0 ? 1.f / s0 : 0.f;
    const float inv1 = v1 ? 1.f / s1 : 0.f;

    // write P = exp(S) as fp16 half2 words (token pairs along the row)
#pragma unroll
    for (int nt = 0; nt < 7; nt++) {
        sp[i0 * 36 + nt * 4 + t] = pack_h2(sc[nt][0], sc[nt][1]);
        sp[i1 * 36 + nt * 4 + t] = pack_h2(sc[nt][2], sc[nt][3]);
    }
    __syncwarp();

    // ---- AV: O[16 x 32] (fp16 mma, K=64 padded -> 4 ko) -------------------
    float ov[4][4];
#pragma unroll
    for (int nt = 0; nt < 4; nt++)
#pragma unroll
        for (int r = 0; r < 4; r++) ov[nt][r] = 0.f;

#pragma unroll
    for (int ko = 0; ko < 4; ko++) {
        const uint32_t a0 = sp[(mtb + g) * 36 + ko * 8 + t];
        const uint32_t a1 = sp[(mtb + g + 8) * 36 + ko * 8 + t];
        const uint32_t a2 = sp[(mtb + g) * 36 + ko * 8 + 4 + t];
        const uint32_t a3 = sp[(mtb + g + 8) * 36 + ko * 8 + 4 + t];
#pragma unroll
        for (int nt = 0; nt < 4; nt++) {
            const uint32_t b0 = svT[(nt * 8 + g) * 36 + ko * 8 + t];
            const uint32_t b1 = svT[(nt * 8 + g) * 36 + ko * 8 + 4 + t];
            asm volatile(
                "mma.sync.aligned.m16n8k16.row.col.f32.f16.f16.f32 "
                "{%0,%1,%2,%3}, {%4,%5,%6,%7}, {%8,%9}, {%0,%1,%2,%3};"
                : "+f"(ov[nt][0]), "+f"(ov[nt][1]), "+f"(ov[nt][2]), "+f"(ov[nt][3])
                : "r"(a0), "r"(a1), "r"(a2), "r"(a3), "r"(b0), "r"(b1));
        }
    }

    // ---- output (fp16, normalized) ----------------------------------------
#pragma unroll
    for (int nt = 0; nt < 4; nt++) {
        const int col = h * 32 + nt * 8 + 2 * t;
        if (v0) {
            *(__half2*)(out + ((size_t)b * NTOK + i0) * CDIM + col) =
                __floats2half2_rn(ov[nt][0] * inv0, ov[nt][1] * inv0);
        }
        if (v1) {
            *(__half2*)(out + ((size_t)b * NTOK + i1) * CDIM + col) =
                __floats2half2_rn(ov[nt][2] * inv1, ov[nt][3] * inv1);
        }
    }
}

// ---------------------------------------------------------------------------
// Launch
// ---------------------------------------------------------------------------
extern "C" void kernel_launch(void* const* d_in, const int* in_sizes, int n_in,
                              void* d_out, int out_size)
{
    const float* x      = (const float*)d_in[0];
    const float* qkv_w  = (const float*)d_in[1];
    const float* qkv_b  = (const float*)d_in[2];
    const float* rpb    = (const float*)d_in[3];
    const float* proj_w = (const float*)d_in[4];
    const float* proj_b = (const float*)d_in[5];
    float* out = (float*)d_out;

    __half* qkvh = nullptr;
    __half* atth = nullptr;
    uint32_t* wqkv = nullptr;
    uint32_t* wproj = nullptr;
    cudaGetSymbolAddress((void**)&qkvh, g_qkv);
    cudaGetSymbolAddress((void**)&atth, g_att);
    cudaGetSymbolAddress((void**)&wqkv, g_wqkv);
    cudaGetSymbolAddress((void**)&wproj, g_wproj);

    constexpr int SMEM = (16 * 8 * 4 * 32 + 2 * 1024) * 4;  // 73728 B
    cudaFuncSetAttribute(h16_gemm<float, __half, 768, 256>,
                         cudaFuncAttributeMaxDynamicSharedMemorySize, SMEM);
    cudaFuncSetAttribute(h16_gemm<__half, float, 256, 256>,
                         cudaFuncAttributeMaxDynamicSharedMemorySize, SMEM);

    // 0) weight conversion to frag-major fp16 (tiny)
    convert_w<<<384, 256>>>(qkv_w, wqkv, 768);
    convert_w<<<128, 256>>>(proj_w, wproj, 256);

    // 1) QKV GEMM (A-resident, fp16 out)
    h16_gemm<float, __half, 768, 256><<<MROWS / 128, 128, SMEM>>>(x, wqkv, qkv_b, qkvh);

    // 2) Windowed attention (pure fp16 tensor cores)
    {
        dim3 grid(BWIN, NHEAD);
        window_attn_h16<<<grid, 128>>>(qkvh, rpb, atth);
    }

    // 3) Projection GEMM (fp16 A, fp32 out)
    h16_gemm<__half, float, 256, 256><<<MROWS / 128, 128, SMEM>>>(atth, wproj, proj_b, out);
}